// round 6
// baseline (speedup 1.0000x reference)
#include <cuda_runtime.h>
#include <cuda_bf16.h>

#define B_     16
#define C_     80
#define D_     1024
#define HW_    196
#define HWP_   208            // hw padded to 13*16
#define NSPL   8
#define DCHUNK (D_ / NSPL)    // 128 d = 64 pairs per block

__device__ float    g_part[B_ * C_ * NSPL * HW_];
__device__ float    g_coef[B_ * C_ * HW_];
__device__ unsigned g_img2[B_ * (D_ / 2) * HWP_];   // f16x2 packed img, hw-padded

__device__ __forceinline__ unsigned pack_h2(float a, float b) {
    unsigned r;
    asm("cvt.rn.f16x2.f32 %0, %2, %1;" : "=r"(r) : "f"(a), "f"(b));
    return r;
}
__device__ __forceinline__ unsigned tanh_h2(unsigned x) {
    unsigned y;
    asm("tanh.approx.f16x2 %0, %1;" : "=r"(y) : "r"(x));
    return y;
}
__device__ __forceinline__ unsigned mul_h2(unsigned a, unsigned b) {
    unsigned y;
    asm("mul.rn.f16x2 %0, %1, %2;" : "=r"(y) : "r"(a), "r"(b));
    return y;
}

// -----------------------------------------------------------------------------
// Kernel P: pack img (f32 [B,D,HW]) -> g_img2 (f16x2 [B,D/2,HWP]), zero pad.
// One thread per (b, dpair, 4 hw). 196 = 4*49 exactly; groups 49..51 are pad.
// -----------------------------------------------------------------------------
__global__ __launch_bounds__(256) void pack_kernel(const float* __restrict__ img)
{
    int idx = blockIdx.x * 256 + threadIdx.x;      // < 16*512*52
    int hw4 = idx % 52;
    int t   = idx / 52;
    int dp  = t & 511;
    int b   = t >> 9;

    uint4 o = make_uint4(0u, 0u, 0u, 0u);
    if (hw4 < 49) {
        const float* p = img + ((size_t)b * D_ + 2 * dp) * HW_ + hw4 * 4;
        float4 a = *(const float4*)p;
        float4 c = *(const float4*)(p + HW_);
        o.x = pack_h2(a.x, c.x);
        o.y = pack_h2(a.y, c.y);
        o.z = pack_h2(a.z, c.z);
        o.w = pack_h2(a.w, c.w);
    }
    *(uint4*)&g_img2[((size_t)b * (D_ / 2) + dp) * HWP_ + hw4 * 4] = o;
}

// -----------------------------------------------------------------------------
// Kernel A: partial[b][c][spl][hw] = sum_{d in chunk} tanh(img*word)*fw
// One-shot per block: cp.async the whole 64-dpair img tile, pack word/fw,
// single barrier, then 8 uninterrupted HMMA steps (m16n8k16, f32 accum).
// grid (13 hw16, 5 c16, B*NSPL), block 128 (4 warps x 4 classes).
// -----------------------------------------------------------------------------
__global__ __launch_bounds__(128) void scores_kernel(
    const float* __restrict__ word,  // [C, D]
    const float* __restrict__ fw)    // [D]
{
    __shared__ unsigned img2_s[64][24];   // [dpair][hw] pad 24 -> conflict-free
    __shared__ unsigned word2_s[16][64];  // [cc][dpair]
    __shared__ unsigned fwh2_s[64];       // [dpair]

    const int tid  = threadIdx.x;
    const int warp = tid >> 5;
    const int lane = tid & 31;
    const int q    = lane & 3;
    const int g    = lane >> 2;
    const int hw0  = blockIdx.x * 16;
    const int c0   = blockIdx.y * 16;
    const int b    = blockIdx.z & (B_ - 1);
    const int spl  = blockIdx.z >> 4;
    const int dp0  = spl * (DCHUNK / 2);   // first dpair of chunk

    // --- img tile via cp.async: 256 x 16B chunks, 2 per thread ---
    {
        unsigned sbase;
        asm("{ .reg .u64 t; cvta.to.shared.u64 t, %1; cvt.u32.u64 %0, t; }"
            : "=r"(sbase) : "l"(&img2_s[0][0]));
        #pragma unroll
        for (int k = 0; k < 2; k++) {
            int ch  = tid + k * 128;       // 0..255
            int dp  = ch >> 2;
            int off = ch & 3;
            unsigned saddr = sbase + (dp * 24 + off * 4) * 4;
            const unsigned* gaddr =
                g_img2 + ((size_t)b * (D_ / 2) + dp0 + dp) * HWP_ + hw0 + off * 4;
            asm volatile("cp.async.ca.shared.global [%0], [%1], 16;"
                         :: "r"(saddr), "l"(gaddr));
        }
        asm volatile("cp.async.commit_group;");
    }

    // --- word tile: 16 cc x 64 dp, 8 u32 per thread ---
    #pragma unroll
    for (int i = tid; i < 1024; i += 128) {
        int cc = i >> 6, dp = i & 63;
        float2 w = *(const float2*)&word[(size_t)(c0 + cc) * D_ + (dp0 + dp) * 2];
        word2_s[cc][dp] = pack_h2(w.x, w.y);
    }
    if (tid < 64)
        fwh2_s[tid] = pack_h2(fw[(dp0 + tid) * 2], fw[(dp0 + tid) * 2 + 1]);

    asm volatile("cp.async.wait_group 0;");
    __syncthreads();

    float dacc[4][4];
    #pragma unroll
    for (int j = 0; j < 4; j++)
        #pragma unroll
        for (int r = 0; r < 4; r++) dacc[j][r] = 0.f;

    const bool bsel = (lane < 4);

    #pragma unroll 4
    for (int kc = 0; kc < 8; kc++) {
        const int p0 = kc * 8 + q;
        const int p1 = p0 + 4;
        const unsigned iv00 = img2_s[p0][g];
        const unsigned iv01 = img2_s[p0][g + 8];
        const unsigned iv10 = img2_s[p1][g];
        const unsigned iv11 = img2_s[p1][g + 8];
        const unsigned fb0 = bsel ? fwh2_s[p0] : 0u;
        const unsigned fb1 = bsel ? fwh2_s[p1] : 0u;

        #pragma unroll
        for (int j = 0; j < 4; j++) {
            const int cl = warp * 4 + j;
            const unsigned wA = word2_s[cl][p0];
            const unsigned wB = word2_s[cl][p1];
            unsigned a0 = tanh_h2(mul_h2(iv00, wA));
            unsigned a1 = tanh_h2(mul_h2(iv01, wA));
            unsigned a2 = tanh_h2(mul_h2(iv10, wB));
            unsigned a3 = tanh_h2(mul_h2(iv11, wB));
            asm("mma.sync.aligned.m16n8k16.row.col.f32.f16.f16.f32 "
                "{%0,%1,%2,%3}, {%4,%5,%6,%7}, {%8,%9}, {%0,%1,%2,%3};"
                : "+f"(dacc[j][0]), "+f"(dacc[j][1]),
                  "+f"(dacc[j][2]), "+f"(dacc[j][3])
                : "r"(a0), "r"(a1), "r"(a2), "r"(a3), "r"(fb0), "r"(fb1));
        }
    }

    if (q == 0) {
        #pragma unroll
        for (int j = 0; j < 4; j++) {
            const int c = c0 + warp * 4 + j;
            const size_t rowbase = (((size_t)b * C_ + c) * NSPL + spl) * HW_;
            const int hw1 = hw0 + g;
            const int hw2 = hw0 + g + 8;
            if (hw1 < HW_) g_part[rowbase + hw1] = dacc[j][0];
            if (hw2 < HW_) g_part[rowbase + hw2] = dacc[j][2];
        }
    }
}

// -----------------------------------------------------------------------------
// Kernel B: sum NSPL partials, softmax over 196 hw -> g_coef. One warp/row.
// -----------------------------------------------------------------------------
__global__ __launch_bounds__(256) void softmax_kernel()
{
    const int wid  = (blockIdx.x * blockDim.x + threadIdx.x) >> 5;
    const int lane = threadIdx.x & 31;
    if (wid >= B_ * C_) return;

    const float* part = g_part + (size_t)wid * NSPL * HW_;
    float* outrow = g_coef + (size_t)wid * HW_;

    float v[7];
    float m = -1e30f;
    #pragma unroll
    for (int k = 0; k < 7; k++) {
        int i = lane + 32 * k;
        float s = -1e30f;
        if (i < HW_) {
            s = 0.f;
            #pragma unroll
            for (int p = 0; p < NSPL; p++) s += part[p * HW_ + i];
        }
        v[k] = s;
        m = fmaxf(m, s);
    }
    #pragma unroll
    for (int o = 16; o; o >>= 1) m = fmaxf(m, __shfl_xor_sync(0xffffffffu, m, o));

    float s = 0.f;
    #pragma unroll
    for (int k = 0; k < 7; k++) { v[k] = __expf(v[k] - m); s += v[k]; }
    #pragma unroll
    for (int o = 16; o; o >>= 1) s += __shfl_xor_sync(0xffffffffu, s, o);

    const float inv = 1.f / s;
    #pragma unroll
    for (int k = 0; k < 7; k++) {
        int i = lane + 32 * k;
        if (i < HW_) outrow[i] = v[k] * inv;
    }
}

// -----------------------------------------------------------------------------
// Kernel C: out[b][c][d] = sum_hw coef[b][c][hw] * img[b][d][hw]
// grid (8 d-tiles of 128, 16 b), block (32,8). f32x2 on adjacent-d pairs.
// -----------------------------------------------------------------------------
#define DT_   128
#define IPAD_ 130
__global__ __launch_bounds__(256) void pool_kernel(
    const float* __restrict__ img,   // [B, D, HW]
    float* __restrict__ out)         // [B, C, D]
{
    extern __shared__ float sm[];
    float* coef_s = sm;                 // [80][196]
    float* img_s  = sm + C_ * HW_;      // [196][IPAD_]

    const int tx  = threadIdx.x;
    const int ty  = threadIdx.y;
    const int tid = ty * 32 + tx;
    const int d0  = blockIdx.x * DT_;
    const int b   = blockIdx.y;

    const float* coefb = g_coef + (size_t)b * C_ * HW_;
    for (int i = tid; i < C_ * HW_; i += 256) coef_s[i] = coefb[i];

    const float* imgb = img + (size_t)b * D_ * HW_;
    for (int i = tid; i < DT_ * HW_; i += 256) {
        int dd = i / HW_, hw = i - dd * HW_;
        img_s[hw * IPAD_ + dd] = imgb[(size_t)(d0 + dd) * HW_ + hw];
    }
    __syncthreads();

    unsigned long long acc[2][10];
    #pragma unroll
    for (int j = 0; j < 2; j++)
        #pragma unroll
        for (int k = 0; k < 10; k++) acc[j][k] = 0ull;

    for (int hw = 0; hw < HW_; hw++) {
        unsigned long long iv[2];
        #pragma unroll
        for (int j = 0; j < 2; j++)
            iv[j] = *(const unsigned long long*)&img_s[hw * IPAD_ + 2 * tx + 64 * j];
        #pragma unroll
        for (int k = 0; k < 10; k++) {
            float cv = coef_s[(ty + 8 * k) * HW_ + hw];
            unsigned long long cv2;
            asm("mov.b64 %0, {%1, %1};" : "=l"(cv2) : "f"(cv));
            #pragma unroll
            for (int j = 0; j < 2; j++)
                asm("fma.rn.f32x2 %0, %1, %2, %0;" : "+l"(acc[j][k]) : "l"(cv2), "l"(iv[j]));
        }
    }

    #pragma unroll
    for (int k = 0; k < 10; k++)
        #pragma unroll
        for (int j = 0; j < 2; j++) {
            float lo, hi;
            asm("mov.b64 {%0, %1}, %2;" : "=f"(lo), "=f"(hi) : "l"(acc[j][k]));
            size_t o = ((size_t)b * C_ + (ty + 8 * k)) * D_ + d0 + 2 * tx + 64 * j;
            *(float2*)&out[o] = make_float2(lo, hi);
        }
}

// -----------------------------------------------------------------------------

extern "C" void kernel_launch(void* const* d_in, const int* in_sizes, int n_in,
                              void* d_out, int out_size)
{
    const float* img  = (const float*)d_in[1];
    const float* word = (const float*)d_in[2];
    const float* fw   = (const float*)d_in[3];
    float* out = (float*)d_out;

    const int pool_smem = (C_ * HW_ + HW_ * IPAD_) * (int)sizeof(float);
    cudaFuncSetAttribute(pool_kernel, cudaFuncAttributeMaxDynamicSharedMemorySize,
                         pool_smem);

    pack_kernel<<<(B_ * (D_ / 2) * 52) / 256, 256>>>(img);

    scores_kernel<<<dim3(13, 5, B_ * NSPL), 128>>>(word, fw);

    softmax_kernel<<<160, 256>>>();

    pool_kernel<<<dim3(D_ / DT_, B_), dim3(32, 8), pool_smem>>>(img, out);
}

// round 7
// speedup vs baseline: 1.0452x; 1.0452x over previous
#include <cuda_runtime.h>
#include <cuda_fp16.h>
#include <cuda_bf16.h>

#define B_     16
#define C_     80
#define D_     1024
#define HW_    196
#define HWP_   208
#define NSPL   8
#define DCHUNK (D_ / NSPL)    // 128 d = 64 pairs per block

__device__ float    g_part[B_ * C_ * NSPL * HW_];
__device__ float    g_coef[B_ * C_ * HW_];
__device__ unsigned g_img2[B_ * (D_ / 2) * HWP_];   // f16x2 packed img (d-pairs)

__device__ __forceinline__ unsigned pack_h2(float a, float b) {
    unsigned r;
    asm("cvt.rn.f16x2.f32 %0, %2, %1;" : "=r"(r) : "f"(a), "f"(b));
    return r;
}
__device__ __forceinline__ unsigned tanh_h2(unsigned x) {
    unsigned y;
    asm("tanh.approx.f16x2 %0, %1;" : "=r"(y) : "r"(x));
    return y;
}
__device__ __forceinline__ unsigned mul_h2(unsigned a, unsigned b) {
    unsigned y;
    asm("mul.rn.f16x2 %0, %1, %2;" : "=r"(y) : "r"(a), "r"(b));
    return y;
}

#define MMA16816(D0,D1,D2,D3, A0,A1,A2,A3, B0,B1) \
    asm("mma.sync.aligned.m16n8k16.row.col.f32.f16.f16.f32 " \
        "{%0,%1,%2,%3}, {%4,%5,%6,%7}, {%8,%9}, {%0,%1,%2,%3};" \
        : "+f"(D0), "+f"(D1), "+f"(D2), "+f"(D3) \
        : "r"(A0), "r"(A1), "r"(A2), "r"(A3), "r"(B0), "r"(B1))

// -----------------------------------------------------------------------------
// Kernel P: pack img (f32 [B,D,HW]) -> g_img2 (f16x2 d-pairs, hw-padded).
// -----------------------------------------------------------------------------
__global__ __launch_bounds__(256) void pack_kernel(const float* __restrict__ img)
{
    int idx = blockIdx.x * 256 + threadIdx.x;
    int hw4 = idx % 52;
    int t   = idx / 52;
    int dp  = t & 511;
    int b   = t >> 9;

    uint4 o = make_uint4(0u, 0u, 0u, 0u);
    if (hw4 < 49) {
        const float* p = img + ((size_t)b * D_ + 2 * dp) * HW_ + hw4 * 4;
        float4 a = *(const float4*)p;
        float4 c = *(const float4*)(p + HW_);
        o.x = pack_h2(a.x, c.x);
        o.y = pack_h2(a.y, c.y);
        o.z = pack_h2(a.z, c.z);
        o.w = pack_h2(a.w, c.w);
    }
    *(uint4*)&g_img2[((size_t)b * (D_ / 2) + dp) * HWP_ + hw4 * 4] = o;
}

// -----------------------------------------------------------------------------
// Kernel A: partial scores via HMMA (one-shot tile, cp.async img).
// grid (13 hw16, 5 c16, B*NSPL), block 128.
// -----------------------------------------------------------------------------
__global__ __launch_bounds__(128) void scores_kernel(
    const float* __restrict__ word,  // [C, D]
    const float* __restrict__ fw)    // [D]
{
    __shared__ unsigned img2_s[64][24];
    __shared__ unsigned word2_s[16][64];
    __shared__ unsigned fwh2_s[64];

    const int tid  = threadIdx.x;
    const int warp = tid >> 5;
    const int lane = tid & 31;
    const int q    = lane & 3;
    const int g    = lane >> 2;
    const int hw0  = blockIdx.x * 16;
    const int c0   = blockIdx.y * 16;
    const int b    = blockIdx.z & (B_ - 1);
    const int spl  = blockIdx.z >> 4;
    const int dp0  = spl * (DCHUNK / 2);

    {
        unsigned sbase;
        asm("{ .reg .u64 t; cvta.to.shared.u64 t, %1; cvt.u32.u64 %0, t; }"
            : "=r"(sbase) : "l"(&img2_s[0][0]));
        #pragma unroll
        for (int k = 0; k < 2; k++) {
            int ch  = tid + k * 128;
            int dp  = ch >> 2;
            int off = ch & 3;
            unsigned saddr = sbase + (dp * 24 + off * 4) * 4;
            const unsigned* gaddr =
                g_img2 + ((size_t)b * (D_ / 2) + dp0 + dp) * HWP_ + hw0 + off * 4;
            asm volatile("cp.async.ca.shared.global [%0], [%1], 16;"
                         :: "r"(saddr), "l"(gaddr));
        }
        asm volatile("cp.async.commit_group;");
    }

    #pragma unroll
    for (int i = tid; i < 1024; i += 128) {
        int cc = i >> 6, dp = i & 63;
        float2 w = *(const float2*)&word[(size_t)(c0 + cc) * D_ + (dp0 + dp) * 2];
        word2_s[cc][dp] = pack_h2(w.x, w.y);
    }
    if (tid < 64)
        fwh2_s[tid] = pack_h2(fw[(dp0 + tid) * 2], fw[(dp0 + tid) * 2 + 1]);

    asm volatile("cp.async.wait_group 0;");
    __syncthreads();

    float dacc[4][4];
    #pragma unroll
    for (int j = 0; j < 4; j++)
        #pragma unroll
        for (int r = 0; r < 4; r++) dacc[j][r] = 0.f;

    const bool bsel = (lane < 4);

    #pragma unroll 4
    for (int kc = 0; kc < 8; kc++) {
        const int p0 = kc * 8 + q;
        const int p1 = p0 + 4;
        const unsigned iv00 = img2_s[p0][g];
        const unsigned iv01 = img2_s[p0][g + 8];
        const unsigned iv10 = img2_s[p1][g];
        const unsigned iv11 = img2_s[p1][g + 8];
        const unsigned fb0 = bsel ? fwh2_s[p0] : 0u;
        const unsigned fb1 = bsel ? fwh2_s[p1] : 0u;

        #pragma unroll
        for (int j = 0; j < 4; j++) {
            const int cl = warp * 4 + j;
            const unsigned wA = word2_s[cl][p0];
            const unsigned wB = word2_s[cl][p1];
            unsigned a0 = tanh_h2(mul_h2(iv00, wA));
            unsigned a1 = tanh_h2(mul_h2(iv01, wA));
            unsigned a2 = tanh_h2(mul_h2(iv10, wB));
            unsigned a3 = tanh_h2(mul_h2(iv11, wB));
            MMA16816(dacc[j][0], dacc[j][1], dacc[j][2], dacc[j][3],
                     a0, a1, a2, a3, fb0, fb1);
        }
    }

    if (q == 0) {
        #pragma unroll
        for (int j = 0; j < 4; j++) {
            const int c = c0 + warp * 4 + j;
            const size_t rowbase = (((size_t)b * C_ + c) * NSPL + spl) * HW_;
            const int hw1 = hw0 + g;
            const int hw2 = hw0 + g + 8;
            if (hw1 < HW_) g_part[rowbase + hw1] = dacc[j][0];
            if (hw2 < HW_) g_part[rowbase + hw2] = dacc[j][2];
        }
    }
}

// -----------------------------------------------------------------------------
// Kernel B: sum NSPL partials, softmax over 196 hw -> g_coef. One warp/row.
// -----------------------------------------------------------------------------
__global__ __launch_bounds__(256) void softmax_kernel()
{
    const int wid  = (blockIdx.x * blockDim.x + threadIdx.x) >> 5;
    const int lane = threadIdx.x & 31;
    if (wid >= B_ * C_) return;

    const float* part = g_part + (size_t)wid * NSPL * HW_;
    float* outrow = g_coef + (size_t)wid * HW_;

    float v[7];
    float m = -1e30f;
    #pragma unroll
    for (int k = 0; k < 7; k++) {
        int i = lane + 32 * k;
        float s = -1e30f;
        if (i < HW_) {
            s = 0.f;
            #pragma unroll
            for (int p = 0; p < NSPL; p++) s += part[p * HW_ + i];
        }
        v[k] = s;
        m = fmaxf(m, s);
    }
    #pragma unroll
    for (int o = 16; o; o >>= 1) m = fmaxf(m, __shfl_xor_sync(0xffffffffu, m, o));

    float s = 0.f;
    #pragma unroll
    for (int k = 0; k < 7; k++) { v[k] = __expf(v[k] - m); s += v[k]; }
    #pragma unroll
    for (int o = 16; o; o >>= 1) s += __shfl_xor_sync(0xffffffffu, s, o);

    const float inv = 1.f / s;
    #pragma unroll
    for (int k = 0; k < 7; k++) {
        int i = lane + 32 * k;
        if (i < HW_) outrow[i] = v[k] * inv;
    }
}

// -----------------------------------------------------------------------------
// Kernel C (HMMA): out[b][:, d-tile] = coef[b] @ img[b,d-tile,:]^T
// Split-f16 (hi+lo) for f32-grade accuracy: AhBh + AhBl + AlBh.
// grid (32 d-tiles of 32, 16 b), block 160 (5 warps = 5 class m16-tiles).
// K = 196 hw padded to 208 = 13 k16 steps.
// -----------------------------------------------------------------------------
#define PDT  32
#define KP   104     // k-pairs
#define KPS  108     // padded row stride (u32) -> conflict-free (108%32=12)

__device__ __forceinline__ void split_h2(float2 v, unsigned& hi, unsigned& lo) {
    __half2 h = __float22half2_rn(v);
    float2 hf = __half22float2(h);
    __half2 l = __float22half2_rn(make_float2(v.x - hf.x, v.y - hf.y));
    hi = *(unsigned*)&h;
    lo = *(unsigned*)&l;
}

__global__ __launch_bounds__(160) void pool_kernel(
    const float* __restrict__ img,   // [B, D, HW]
    float* __restrict__ out)         // [B, C, D]
{
    extern __shared__ unsigned psm[];
    unsigned* ch = psm;                      // coef hi [80][KPS]
    unsigned* cl = ch + C_ * KPS;            // coef lo
    unsigned* ih = cl + C_ * KPS;            // img  hi [PDT][KPS]
    unsigned* il = ih + PDT * KPS;           // img  lo

    const int tid  = threadIdx.x;
    const int warp = tid >> 5;               // 0..4 -> class m-tile
    const int lane = tid & 31;
    const int q    = lane & 3;
    const int g    = lane >> 2;              // 0..7
    const int d0   = blockIdx.x * PDT;
    const int b    = blockIdx.y;

    const float* coefb = g_coef + (size_t)b * C_ * HW_;
    for (int i = tid; i < C_ * KP; i += 160) {
        int c = i / KP, kp = i - c * KP;
        float2 v = make_float2(0.f, 0.f);
        if (kp < 98) v = *(const float2*)&coefb[c * HW_ + 2 * kp];
        split_h2(v, ch[c * KPS + kp], cl[c * KPS + kp]);
    }
    const float* imgb = img + ((size_t)b * D_ + d0) * HW_;
    for (int i = tid; i < PDT * KP; i += 160) {
        int dd = i / KP, kp = i - dd * KP;
        float2 v = make_float2(0.f, 0.f);
        if (kp < 98) v = *(const float2*)&imgb[dd * HW_ + 2 * kp];
        split_h2(v, ih[dd * KPS + kp], il[dd * KPS + kp]);
    }
    __syncthreads();

    float acc[4][4];
    #pragma unroll
    for (int t = 0; t < 4; t++)
        #pragma unroll
        for (int r = 0; r < 4; r++) acc[t][r] = 0.f;

    const int rA0 = (warp * 16 + g) * KPS;
    const int rA1 = (warp * 16 + g + 8) * KPS;

    #pragma unroll 1
    for (int ks = 0; ks < 13; ks++) {
        const int p0 = ks * 8 + q;
        const int p1 = p0 + 4;
        const unsigned ah0 = ch[rA0 + p0], ah1 = ch[rA1 + p0];
        const unsigned ah2 = ch[rA0 + p1], ah3 = ch[rA1 + p1];
        const unsigned al0 = cl[rA0 + p0], al1 = cl[rA1 + p0];
        const unsigned al2 = cl[rA0 + p1], al3 = cl[rA1 + p1];

        #pragma unroll
        for (int t = 0; t < 4; t++) {
            const int rB = (t * 8 + g) * KPS;
            const unsigned bh0 = ih[rB + p0], bh1 = ih[rB + p1];
            const unsigned bl0 = il[rB + p0], bl1 = il[rB + p1];
            MMA16816(acc[t][0], acc[t][1], acc[t][2], acc[t][3],
                     ah0, ah1, ah2, ah3, bh0, bh1);
            MMA16816(acc[t][0], acc[t][1], acc[t][2], acc[t][3],
                     ah0, ah1, ah2, ah3, bl0, bl1);
            MMA16816(acc[t][0], acc[t][1], acc[t][2], acc[t][3],
                     al0, al1, al2, al3, bh0, bh1);
        }
    }

    #pragma unroll
    for (int t = 0; t < 4; t++) {
        const int dcol = d0 + t * 8 + 2 * q;
        const size_t r0 = ((size_t)b * C_ + warp * 16 + g) * D_ + dcol;
        const size_t r1 = ((size_t)b * C_ + warp * 16 + g + 8) * D_ + dcol;
        *(float2*)&out[r0] = make_float2(acc[t][0], acc[t][1]);
        *(float2*)&out[r1] = make_float2(acc[t][2], acc[t][3]);
    }
}

// -----------------------------------------------------------------------------

extern "C" void kernel_launch(void* const* d_in, const int* in_sizes, int n_in,
                              void* d_out, int out_size)
{
    const float* img  = (const float*)d_in[1];
    const float* word = (const float*)d_in[2];
    const float* fw   = (const float*)d_in[3];
    float* out = (float*)d_out;

    const int pool_smem = 2 * (C_ + PDT) * KPS * (int)sizeof(unsigned); // 96768 B
    cudaFuncSetAttribute(pool_kernel, cudaFuncAttributeMaxDynamicSharedMemorySize,
                         pool_smem);

    pack_kernel<<<(B_ * (D_ / 2) * 52) / 256, 256>>>(img);

    scores_kernel<<<dim3(13, 5, B_ * NSPL), 128>>>(word, fw);

    softmax_kernel<<<160, 256>>>();

    pool_kernel<<<dim3(D_ / PDT, B_), 160, pool_smem>>>(img, out);
}

// round 8
// speedup vs baseline: 1.0663x; 1.0202x over previous
#include <cuda_runtime.h>
#include <cuda_fp16.h>
#include <cuda_bf16.h>

#define B_     16
#define C_     80
#define D_     1024
#define HW_    196
#define HWP_   208
#define NSPL   8
#define DCHUNK (D_ / NSPL)    // 128 d = 64 pairs per block
#define KP_    104            // hw-pairs (208/2)

__device__ float    g_part[B_ * C_ * NSPL * HW_];
__device__ unsigned g_img2[B_ * (D_ / 2) * HWP_];     // f16x2 d-pairs (for scores)
__device__ unsigned g_coef_hi[B_ * C_ * KP_];         // f16x2 hw-pairs
__device__ unsigned g_coef_lo[B_ * C_ * KP_];
__device__ unsigned g_imgT_hi[B_ * D_ * KP_];         // f16x2 hw-pairs
__device__ unsigned g_imgT_lo[B_ * D_ * KP_];

__device__ __forceinline__ unsigned pack_h2(float a, float b) {
    unsigned r;
    asm("cvt.rn.f16x2.f32 %0, %2, %1;" : "=r"(r) : "f"(a), "f"(b));
    return r;
}
__device__ __forceinline__ unsigned tanh_h2(unsigned x) {
    unsigned y;
    asm("tanh.approx.f16x2 %0, %1;" : "=r"(y) : "r"(x));
    return y;
}
__device__ __forceinline__ unsigned mul_h2(unsigned a, unsigned b) {
    unsigned y;
    asm("mul.rn.f16x2 %0, %1, %2;" : "=r"(y) : "r"(a), "r"(b));
    return y;
}
__device__ __forceinline__ void split_h2(float2 v, unsigned& hi, unsigned& lo) {
    __half2 h = __float22half2_rn(v);
    float2 hf = __half22float2(h);
    __half2 l = __float22half2_rn(make_float2(v.x - hf.x, v.y - hf.y));
    hi = *(unsigned*)&h;
    lo = *(unsigned*)&l;
}

#define MMA16816(D0,D1,D2,D3, A0,A1,A2,A3, B0,B1) \
    asm("mma.sync.aligned.m16n8k16.row.col.f32.f16.f16.f32 " \
        "{%0,%1,%2,%3}, {%4,%5,%6,%7}, {%8,%9}, {%0,%1,%2,%3};" \
        : "+f"(D0), "+f"(D1), "+f"(D2), "+f"(D3) \
        : "r"(A0), "r"(A1), "r"(A2), "r"(A3), "r"(B0), "r"(B1))

// -----------------------------------------------------------------------------
// Kernel P1: pack img -> g_img2 (f16x2 d-pairs, hw-padded)  [for scores]
// -----------------------------------------------------------------------------
__global__ __launch_bounds__(256) void pack_kernel(const float* __restrict__ img)
{
    int idx = blockIdx.x * 256 + threadIdx.x;
    int hw4 = idx % 52;
    int t   = idx / 52;
    int dp  = t & 511;
    int b   = t >> 9;

    uint4 o = make_uint4(0u, 0u, 0u, 0u);
    if (hw4 < 49) {
        const float* p = img + ((size_t)b * D_ + 2 * dp) * HW_ + hw4 * 4;
        float4 a = *(const float4*)p;
        float4 c = *(const float4*)(p + HW_);
        o.x = pack_h2(a.x, c.x);
        o.y = pack_h2(a.y, c.y);
        o.z = pack_h2(a.z, c.z);
        o.w = pack_h2(a.w, c.w);
    }
    *(uint4*)&g_img2[((size_t)b * (D_ / 2) + dp) * HWP_ + hw4 * 4] = o;
}

// -----------------------------------------------------------------------------
// Kernel P2: pack img -> g_imgT hi/lo (f16x2 hw-pairs per d row)  [for pool]
// thread = (b, d, ks<13): 16 hw = 8 pairs.  196 = 12*16 + 4 tail.
// -----------------------------------------------------------------------------
__global__ __launch_bounds__(256) void pack2_kernel(const float* __restrict__ img)
{
    int idx = blockIdx.x * 256 + threadIdx.x;   // < 16*1024*13
    int ks = idx % 13;
    int t  = idx / 13;
    int d  = t & (D_ - 1);
    int b  = t >> 10;

    const float* row = img + ((size_t)b * D_ + d) * HW_;
    float v[16];
    if (ks < 12) {
        #pragma unroll
        for (int j = 0; j < 4; j++) {
            float4 f = *(const float4*)(row + ks * 16 + j * 4);
            v[4*j] = f.x; v[4*j+1] = f.y; v[4*j+2] = f.z; v[4*j+3] = f.w;
        }
    } else {
        float4 f = *(const float4*)(row + 192);
        v[0] = f.x; v[1] = f.y; v[2] = f.z; v[3] = f.w;
        #pragma unroll
        for (int j = 4; j < 16; j++) v[j] = 0.f;
    }
    unsigned hi[8], lo[8];
    #pragma unroll
    for (int j = 0; j < 8; j++)
        split_h2(make_float2(v[2*j], v[2*j+1]), hi[j], lo[j]);

    unsigned* ph = g_imgT_hi + ((size_t)b * D_ + d) * KP_ + ks * 8;
    unsigned* pl = g_imgT_lo + ((size_t)b * D_ + d) * KP_ + ks * 8;
    *(uint4*)ph       = make_uint4(hi[0], hi[1], hi[2], hi[3]);
    *(uint4*)(ph + 4) = make_uint4(hi[4], hi[5], hi[6], hi[7]);
    *(uint4*)pl       = make_uint4(lo[0], lo[1], lo[2], lo[3]);
    *(uint4*)(pl + 4) = make_uint4(lo[4], lo[5], lo[6], lo[7]);
}

// -----------------------------------------------------------------------------
// Kernel A: partial scores via HMMA (one-shot tile, cp.async img). Unchanged.
// -----------------------------------------------------------------------------
__global__ __launch_bounds__(128) void scores_kernel(
    const float* __restrict__ word,  // [C, D]
    const float* __restrict__ fw)    // [D]
{
    __shared__ unsigned img2_s[64][24];
    __shared__ unsigned word2_s[16][64];
    __shared__ unsigned fwh2_s[64];

    const int tid  = threadIdx.x;
    const int warp = tid >> 5;
    const int lane = tid & 31;
    const int q    = lane & 3;
    const int g    = lane >> 2;
    const int hw0  = blockIdx.x * 16;
    const int c0   = blockIdx.y * 16;
    const int b    = blockIdx.z & (B_ - 1);
    const int spl  = blockIdx.z >> 4;
    const int dp0  = spl * (DCHUNK / 2);

    {
        unsigned sbase;
        asm("{ .reg .u64 t; cvta.to.shared.u64 t, %1; cvt.u32.u64 %0, t; }"
            : "=r"(sbase) : "l"(&img2_s[0][0]));
        #pragma unroll
        for (int k = 0; k < 2; k++) {
            int ch  = tid + k * 128;
            int dp  = ch >> 2;
            int off = ch & 3;
            unsigned saddr = sbase + (dp * 24 + off * 4) * 4;
            const unsigned* gaddr =
                g_img2 + ((size_t)b * (D_ / 2) + dp0 + dp) * HWP_ + hw0 + off * 4;
            asm volatile("cp.async.ca.shared.global [%0], [%1], 16;"
                         :: "r"(saddr), "l"(gaddr));
        }
        asm volatile("cp.async.commit_group;");
    }

    #pragma unroll
    for (int i = tid; i < 1024; i += 128) {
        int cc = i >> 6, dp = i & 63;
        float2 w = *(const float2*)&word[(size_t)(c0 + cc) * D_ + (dp0 + dp) * 2];
        word2_s[cc][dp] = pack_h2(w.x, w.y);
    }
    if (tid < 64)
        fwh2_s[tid] = pack_h2(fw[(dp0 + tid) * 2], fw[(dp0 + tid) * 2 + 1]);

    asm volatile("cp.async.wait_group 0;");
    __syncthreads();

    float dacc[4][4];
    #pragma unroll
    for (int j = 0; j < 4; j++)
        #pragma unroll
        for (int r = 0; r < 4; r++) dacc[j][r] = 0.f;

    const bool bsel = (lane < 4);

    #pragma unroll 4
    for (int kc = 0; kc < 8; kc++) {
        const int p0 = kc * 8 + q;
        const int p1 = p0 + 4;
        const unsigned iv00 = img2_s[p0][g];
        const unsigned iv01 = img2_s[p0][g + 8];
        const unsigned iv10 = img2_s[p1][g];
        const unsigned iv11 = img2_s[p1][g + 8];
        const unsigned fb0 = bsel ? fwh2_s[p0] : 0u;
        const unsigned fb1 = bsel ? fwh2_s[p1] : 0u;

        #pragma unroll
        for (int j = 0; j < 4; j++) {
            const int cl = warp * 4 + j;
            const unsigned wA = word2_s[cl][p0];
            const unsigned wB = word2_s[cl][p1];
            unsigned a0 = tanh_h2(mul_h2(iv00, wA));
            unsigned a1 = tanh_h2(mul_h2(iv01, wA));
            unsigned a2 = tanh_h2(mul_h2(iv10, wB));
            unsigned a3 = tanh_h2(mul_h2(iv11, wB));
            MMA16816(dacc[j][0], dacc[j][1], dacc[j][2], dacc[j][3],
                     a0, a1, a2, a3, fb0, fb1);
        }
    }

    if (q == 0) {
        #pragma unroll
        for (int j = 0; j < 4; j++) {
            const int c = c0 + warp * 4 + j;
            const size_t rowbase = (((size_t)b * C_ + c) * NSPL + spl) * HW_;
            const int hw1 = hw0 + g;
            const int hw2 = hw0 + g + 8;
            if (hw1 < HW_) g_part[rowbase + hw1] = dacc[j][0];
            if (hw2 < HW_) g_part[rowbase + hw2] = dacc[j][2];
        }
    }
}

// -----------------------------------------------------------------------------
// Kernel B: sum NSPL partials, softmax, emit coef as split hi/lo f16x2 pairs.
// One warp per (b,c) row.
// -----------------------------------------------------------------------------
__global__ __launch_bounds__(256) void softmax_kernel()
{
    const int wid  = (blockIdx.x * blockDim.x + threadIdx.x) >> 5;
    const int lane = threadIdx.x & 31;
    if (wid >= B_ * C_) return;

    const float* part = g_part + (size_t)wid * NSPL * HW_;

    float v[7];
    float m = -1e30f;
    #pragma unroll
    for (int k = 0; k < 7; k++) {
        int i = lane + 32 * k;
        float s = -1e30f;
        if (i < HW_) {
            s = 0.f;
            #pragma unroll
            for (int p = 0; p < NSPL; p++) s += part[p * HW_ + i];
        }
        v[k] = s;
        m = fmaxf(m, s);
    }
    #pragma unroll
    for (int o = 16; o; o >>= 1) m = fmaxf(m, __shfl_xor_sync(0xffffffffu, m, o));

    float s = 0.f;
    #pragma unroll
    for (int k = 0; k < 7; k++) { v[k] = __expf(v[k] - m); s += v[k]; }
    #pragma unroll
    for (int o = 16; o; o >>= 1) s += __shfl_xor_sync(0xffffffffu, s, o);

    const float inv = 1.f / s;
    unsigned* ph = g_coef_hi + (size_t)wid * KP_;
    unsigned* pl = g_coef_lo + (size_t)wid * KP_;
    #pragma unroll
    for (int k = 0; k < 7; k++) {
        float mine = v[k] * inv;                        // 0 for padded i
        float partner = __shfl_xor_sync(0xffffffffu, mine, 1);
        int kp = (lane >> 1) + 16 * k;
        if ((lane & 1) == 0 && kp < KP_) {
            unsigned hi, lo;
            split_h2(make_float2(mine, partner), hi, lo);
            ph[kp] = hi;
            pl[kp] = lo;
        }
    }
}

// -----------------------------------------------------------------------------
// Kernel C (HMMA pool): out[b][:, d-tile] = coef[b] @ img[b,d-tile,:]^T
// Fill is pure cp.async from pre-split hi/lo arrays. One barrier, then MMAs.
// grid (32 d-tiles of 32, 16 b), block 160 (5 warps = 5 class m16-tiles).
// -----------------------------------------------------------------------------
#define PDT  32
#define KPS  108     // smem row stride (u32): conflict-free, 16B-aligned rows

__global__ __launch_bounds__(160) void pool_kernel(float* __restrict__ out)
{
    extern __shared__ unsigned psm[];
    unsigned* ch = psm;                      // coef hi [80][KPS]
    unsigned* cl = ch + C_ * KPS;            // coef lo
    unsigned* ih = cl + C_ * KPS;            // img  hi [PDT][KPS]
    unsigned* il = ih + PDT * KPS;           // img  lo

    const int tid  = threadIdx.x;
    const int warp = tid >> 5;
    const int lane = tid & 31;
    const int q    = lane & 3;
    const int g    = lane >> 2;
    const int d0   = blockIdx.x * PDT;
    const int b    = blockIdx.y;

    unsigned sbase;
    asm("{ .reg .u64 t; cvta.to.shared.u64 t, %1; cvt.u32.u64 %0, t; }"
        : "=r"(sbase) : "l"(psm));

    // coef hi+lo: 80 rows x 26 chunks x 2 arrays
    for (int i = tid; i < C_ * 26; i += 160) {
        int row = i / 26, cq = i - row * 26;
        unsigned soff = (row * KPS + cq * 4) * 4;
        size_t  goff = ((size_t)b * C_ + row) * KP_ + cq * 4;
        asm volatile("cp.async.ca.shared.global [%0], [%1], 16;"
                     :: "r"(sbase + soff), "l"(g_coef_hi + goff));
        asm volatile("cp.async.ca.shared.global [%0], [%1], 16;"
                     :: "r"(sbase + (unsigned)(C_ * KPS * 4) + soff),
                        "l"(g_coef_lo + goff));
    }
    // img hi+lo: 32 rows x 26 chunks x 2 arrays
    const unsigned ih_off = 2u * C_ * KPS * 4;
    for (int i = tid; i < PDT * 26; i += 160) {
        int row = i / 26, cq = i - row * 26;
        unsigned soff = (row * KPS + cq * 4) * 4;
        size_t  goff = ((size_t)b * D_ + d0 + row) * KP_ + cq * 4;
        asm volatile("cp.async.ca.shared.global [%0], [%1], 16;"
                     :: "r"(sbase + ih_off + soff), "l"(g_imgT_hi + goff));
        asm volatile("cp.async.ca.shared.global [%0], [%1], 16;"
                     :: "r"(sbase + ih_off + (unsigned)(PDT * KPS * 4) + soff),
                        "l"(g_imgT_lo + goff));
    }
    asm volatile("cp.async.commit_group;");
    asm volatile("cp.async.wait_group 0;");
    __syncthreads();

    float acc[4][4];
    #pragma unroll
    for (int t = 0; t < 4; t++)
        #pragma unroll
        for (int r = 0; r < 4; r++) acc[t][r] = 0.f;

    const int rA0 = (warp * 16 + g) * KPS;
    const int rA1 = (warp * 16 + g + 8) * KPS;

    #pragma unroll 1
    for (int ks = 0; ks < 13; ks++) {
        const int p0 = ks * 8 + q;
        const int p1 = p0 + 4;
        const unsigned ah0 = ch[rA0 + p0], ah1 = ch[rA1 + p0];
        const unsigned ah2 = ch[rA0 + p1], ah3 = ch[rA1 + p1];
        const unsigned al0 = cl[rA0 + p0], al1 = cl[rA1 + p0];
        const unsigned al2 = cl[rA0 + p1], al3 = cl[rA1 + p1];

        #pragma unroll
        for (int t = 0; t < 4; t++) {
            const int rB = (t * 8 + g) * KPS;
            const unsigned bh0 = ih[rB + p0], bh1 = ih[rB + p1];
            const unsigned bl0 = il[rB + p0], bl1 = il[rB + p1];
            MMA16816(acc[t][0], acc[t][1], acc[t][2], acc[t][3],
                     ah0, ah1, ah2, ah3, bh0, bh1);
            MMA16816(acc[t][0], acc[t][1], acc[t][2], acc[t][3],
                     ah0, ah1, ah2, ah3, bl0, bl1);
            MMA16816(acc[t][0], acc[t][1], acc[t][2], acc[t][3],
                     al0, al1, al2, al3, bh0, bh1);
        }
    }

    #pragma unroll
    for (int t = 0; t < 4; t++) {
        const int dcol = d0 + t * 8 + 2 * q;
        const size_t r0 = ((size_t)b * C_ + warp * 16 + g) * D_ + dcol;
        const size_t r1 = ((size_t)b * C_ + warp * 16 + g + 8) * D_ + dcol;
        *(float2*)&out[r0] = make_float2(acc[t][0], acc[t][1]);
        *(float2*)&out[r1] = make_float2(acc[t][2], acc[t][3]);
    }
}

// -----------------------------------------------------------------------------

extern "C" void kernel_launch(void* const* d_in, const int* in_sizes, int n_in,
                              void* d_out, int out_size)
{
    const float* img  = (const float*)d_in[1];
    const float* word = (const float*)d_in[2];
    const float* fw   = (const float*)d_in[3];
    float* out = (float*)d_out;

    const int pool_smem = (2 * C_ + 2 * PDT) * KPS * (int)sizeof(unsigned); // 96768
    cudaFuncSetAttribute(pool_kernel, cudaFuncAttributeMaxDynamicSharedMemorySize,
                         pool_smem);

    pack_kernel<<<(B_ * (D_ / 2) * 52) / 256, 256>>>(img);
    pack2_kernel<<<(B_ * D_ * 13) / 256, 256>>>(img);

    scores_kernel<<<dim3(13, 5, B_ * NSPL), 128>>>(word, fw);

    softmax_kernel<<<160, 256>>>();

    pool_kernel<<<dim3(D_ / PDT, B_), 160, pool_smem>>>(out);
}

// round 9
// speedup vs baseline: 1.0915x; 1.0236x over previous
#include <cuda_runtime.h>
#include <cuda_fp16.h>
#include <cuda_bf16.h>

#define B_     16
#define C_     80
#define D_     1024
#define HW_    196
#define HWP_   208
#define NSPL   4
#define DCHUNK (D_ / NSPL)    // 256 d = 128 pairs per scores block
#define KP_    104            // hw-pairs (208/2)

__device__ float    g_part[B_ * C_ * NSPL * HW_];
__device__ unsigned g_img2[B_ * (D_ / 2) * HWP_];     // f16x2 d-pairs (scores)
__device__ unsigned g_word2[C_ * (D_ / 2)];           // f16x2 d-pairs (scores)
__device__ unsigned g_fwh2[D_ / 2];                   // f16x2 d-pairs (scores)
__device__ unsigned g_coef_hi[B_ * C_ * KP_];         // f16x2 hw-pairs (pool)
__device__ unsigned g_coef_lo[B_ * C_ * KP_];
__device__ unsigned g_imgT_hi[B_ * D_ * KP_];         // f16x2 hw-pairs (pool)
__device__ unsigned g_imgT_lo[B_ * D_ * KP_];

__device__ __forceinline__ unsigned pack_h2(float a, float b) {
    unsigned r;
    asm("cvt.rn.f16x2.f32 %0, %2, %1;" : "=r"(r) : "f"(a), "f"(b));
    return r;
}
__device__ __forceinline__ unsigned tanh_h2(unsigned x) {
    unsigned y;
    asm("tanh.approx.f16x2 %0, %1;" : "=r"(y) : "r"(x));
    return y;
}
__device__ __forceinline__ unsigned mul_h2(unsigned a, unsigned b) {
    unsigned y;
    asm("mul.rn.f16x2 %0, %1, %2;" : "=r"(y) : "r"(a), "r"(b));
    return y;
}
__device__ __forceinline__ void split_h2(float2 v, unsigned& hi, unsigned& lo) {
    __half2 h = __float22half2_rn(v);
    float2 hf = __half22float2(h);
    __half2 l = __float22half2_rn(make_float2(v.x - hf.x, v.y - hf.y));
    hi = *(unsigned*)&h;
    lo = *(unsigned*)&l;
}

#define MMA16816(D0,D1,D2,D3, A0,A1,A2,A3, B0,B1) \
    asm("mma.sync.aligned.m16n8k16.row.col.f32.f16.f16.f32 " \
        "{%0,%1,%2,%3}, {%4,%5,%6,%7}, {%8,%9}, {%0,%1,%2,%3};" \
        : "+f"(D0), "+f"(D1), "+f"(D2), "+f"(D3) \
        : "r"(A0), "r"(A1), "r"(A2), "r"(A3), "r"(B0), "r"(B1))

// -----------------------------------------------------------------------------
// Kernel P (merged): phase 1 -> g_img2, phase 2 -> g_imgT hi/lo,
// phase 3 -> g_word2 + g_fwh2.
// -----------------------------------------------------------------------------
#define P1_BLOCKS 1664   // 16*512*52 / 256
#define P2_BLOCKS 832    // 16*1024*13 / 256
#define P3_BLOCKS 162    // (80*512 + 512) / 256
__global__ __launch_bounds__(256) void pack_all(
    const float* __restrict__ img,
    const float* __restrict__ word,
    const float* __restrict__ fw)
{
    const int blk = blockIdx.x;
    const int tid = threadIdx.x;

    if (blk < P1_BLOCKS) {
        int idx = blk * 256 + tid;
        int hw4 = idx % 52;
        int t   = idx / 52;
        int dp  = t & 511;
        int b   = t >> 9;
        uint4 o = make_uint4(0u, 0u, 0u, 0u);
        if (hw4 < 49) {
            const float* p = img + ((size_t)b * D_ + 2 * dp) * HW_ + hw4 * 4;
            float4 a = *(const float4*)p;
            float4 c = *(const float4*)(p + HW_);
            o.x = pack_h2(a.x, c.x);
            o.y = pack_h2(a.y, c.y);
            o.z = pack_h2(a.z, c.z);
            o.w = pack_h2(a.w, c.w);
        }
        *(uint4*)&g_img2[((size_t)b * (D_ / 2) + dp) * HWP_ + hw4 * 4] = o;
    } else if (blk < P1_BLOCKS + P2_BLOCKS) {
        int idx = (blk - P1_BLOCKS) * 256 + tid;
        int ks = idx % 13;
        int t  = idx / 13;
        int d  = t & (D_ - 1);
        int b  = t >> 10;
        const float* row = img + ((size_t)b * D_ + d) * HW_;
        float v[16];
        if (ks < 12) {
            #pragma unroll
            for (int j = 0; j < 4; j++) {
                float4 f = *(const float4*)(row + ks * 16 + j * 4);
                v[4*j] = f.x; v[4*j+1] = f.y; v[4*j+2] = f.z; v[4*j+3] = f.w;
            }
        } else {
            float4 f = *(const float4*)(row + 192);
            v[0] = f.x; v[1] = f.y; v[2] = f.z; v[3] = f.w;
            #pragma unroll
            for (int j = 4; j < 16; j++) v[j] = 0.f;
        }
        unsigned hi[8], lo[8];
        #pragma unroll
        for (int j = 0; j < 8; j++)
            split_h2(make_float2(v[2*j], v[2*j+1]), hi[j], lo[j]);
        unsigned* ph = g_imgT_hi + ((size_t)b * D_ + d) * KP_ + ks * 8;
        unsigned* pl = g_imgT_lo + ((size_t)b * D_ + d) * KP_ + ks * 8;
        *(uint4*)ph       = make_uint4(hi[0], hi[1], hi[2], hi[3]);
        *(uint4*)(ph + 4) = make_uint4(hi[4], hi[5], hi[6], hi[7]);
        *(uint4*)pl       = make_uint4(lo[0], lo[1], lo[2], lo[3]);
        *(uint4*)(pl + 4) = make_uint4(lo[4], lo[5], lo[6], lo[7]);
    } else {
        int idx = (blk - P1_BLOCKS - P2_BLOCKS) * 256 + tid;
        if (idx < C_ * (D_ / 2)) {
            int c = idx >> 9, dp = idx & 511;
            float2 w = *(const float2*)&word[(size_t)c * D_ + 2 * dp];
            g_word2[c * (D_ / 2) + dp] = pack_h2(w.x, w.y);
        } else {
            int dp = idx - C_ * (D_ / 2);   // < 512
            g_fwh2[dp] = pack_h2(fw[2 * dp], fw[2 * dp + 1]);
        }
    }
}

// -----------------------------------------------------------------------------
// Kernel A: partial scores via HMMA. Fill = pure cp.async (img/word/fw all
// pre-packed). grid (13 hw16, 5 c16, B*NSPL), block 128. 16 kc steps.
// -----------------------------------------------------------------------------
__global__ __launch_bounds__(128) void scores_kernel()
{
    __shared__ unsigned img2_s[128][24];    // [dpair][hw] pad 24
    __shared__ unsigned word2_s[16][128];   // [cc][dpair]
    __shared__ unsigned fwh2_s[128];

    const int tid  = threadIdx.x;
    const int warp = tid >> 5;
    const int lane = tid & 31;
    const int q    = lane & 3;
    const int g    = lane >> 2;
    const int hw0  = blockIdx.x * 16;
    const int c0   = blockIdx.y * 16;
    const int b    = blockIdx.z & (B_ - 1);
    const int spl  = blockIdx.z >> 4;
    const int dp0  = spl * (DCHUNK / 2);    // 128-dpair chunk

    unsigned sb_img, sb_word, sb_fw;
    asm("{ .reg .u64 t; cvta.to.shared.u64 t, %1; cvt.u32.u64 %0, t; }"
        : "=r"(sb_img) : "l"(&img2_s[0][0]));
    asm("{ .reg .u64 t; cvta.to.shared.u64 t, %1; cvt.u32.u64 %0, t; }"
        : "=r"(sb_word) : "l"(&word2_s[0][0]));
    asm("{ .reg .u64 t; cvta.to.shared.u64 t, %1; cvt.u32.u64 %0, t; }"
        : "=r"(sb_fw) : "l"(&fwh2_s[0]));

    // img: 128 rows x 4 chunks (16B) = 512
    #pragma unroll
    for (int k = 0; k < 4; k++) {
        int ch  = tid + k * 128;
        int dp  = ch >> 2;
        int off = ch & 3;
        asm volatile("cp.async.ca.shared.global [%0], [%1], 16;"
            :: "r"(sb_img + (dp * 24 + off * 4) * 4),
               "l"(g_img2 + ((size_t)b * (D_ / 2) + dp0 + dp) * HWP_ + hw0 + off * 4));
    }
    // word: 16 rows x 32 chunks = 512
    #pragma unroll
    for (int k = 0; k < 4; k++) {
        int ch = tid + k * 128;
        int row = ch >> 5;
        int cq  = ch & 31;
        asm volatile("cp.async.ca.shared.global [%0], [%1], 16;"
            :: "r"(sb_word + (row * 128 + cq * 4) * 4),
               "l"(g_word2 + (size_t)(c0 + row) * (D_ / 2) + dp0 + cq * 4));
    }
    if (tid < 32)
        asm volatile("cp.async.ca.shared.global [%0], [%1], 16;"
            :: "r"(sb_fw + tid * 16), "l"(g_fwh2 + dp0 + tid * 4));

    asm volatile("cp.async.commit_group;");
    asm volatile("cp.async.wait_group 0;");
    __syncthreads();

    float dacc[4][4];
    #pragma unroll
    for (int j = 0; j < 4; j++)
        #pragma unroll
        for (int r = 0; r < 4; r++) dacc[j][r] = 0.f;

    const bool bsel = (lane < 4);

    #pragma unroll 4
    for (int kc = 0; kc < 16; kc++) {
        const int p0 = kc * 8 + q;
        const int p1 = p0 + 4;
        const unsigned iv00 = img2_s[p0][g];
        const unsigned iv01 = img2_s[p0][g + 8];
        const unsigned iv10 = img2_s[p1][g];
        const unsigned iv11 = img2_s[p1][g + 8];
        const unsigned fb0 = bsel ? fwh2_s[p0] : 0u;
        const unsigned fb1 = bsel ? fwh2_s[p1] : 0u;

        #pragma unroll
        for (int j = 0; j < 4; j++) {
            const int cl = warp * 4 + j;
            const unsigned wA = word2_s[cl][p0];
            const unsigned wB = word2_s[cl][p1];
            unsigned a0 = tanh_h2(mul_h2(iv00, wA));
            unsigned a1 = tanh_h2(mul_h2(iv01, wA));
            unsigned a2 = tanh_h2(mul_h2(iv10, wB));
            unsigned a3 = tanh_h2(mul_h2(iv11, wB));
            MMA16816(dacc[j][0], dacc[j][1], dacc[j][2], dacc[j][3],
                     a0, a1, a2, a3, fb0, fb1);
        }
    }

    if (q == 0) {
        #pragma unroll
        for (int j = 0; j < 4; j++) {
            const int c = c0 + warp * 4 + j;
            const size_t rowbase = (((size_t)b * C_ + c) * NSPL + spl) * HW_;
            const int hw1 = hw0 + g;
            const int hw2 = hw0 + g + 8;
            if (hw1 < HW_) g_part[rowbase + hw1] = dacc[j][0];
            if (hw2 < HW_) g_part[rowbase + hw2] = dacc[j][2];
        }
    }
}

// -----------------------------------------------------------------------------
// Kernel B: sum NSPL partials, softmax, emit coef hi/lo f16x2 pairs.
// -----------------------------------------------------------------------------
__global__ __launch_bounds__(256) void softmax_kernel()
{
    const int wid  = (blockIdx.x * blockDim.x + threadIdx.x) >> 5;
    const int lane = threadIdx.x & 31;
    if (wid >= B_ * C_) return;

    const float* part = g_part + (size_t)wid * NSPL * HW_;

    float v[7];
    float m = -1e30f;
    #pragma unroll
    for (int k = 0; k < 7; k++) {
        int i = lane + 32 * k;
        float s = -1e30f;
        if (i < HW_) {
            s = 0.f;
            #pragma unroll
            for (int p = 0; p < NSPL; p++) s += part[p * HW_ + i];
        }
        v[k] = s;
        m = fmaxf(m, s);
    }
    #pragma unroll
    for (int o = 16; o; o >>= 1) m = fmaxf(m, __shfl_xor_sync(0xffffffffu, m, o));

    float s = 0.f;
    #pragma unroll
    for (int k = 0; k < 7; k++) { v[k] = __expf(v[k] - m); s += v[k]; }
    #pragma unroll
    for (int o = 16; o; o >>= 1) s += __shfl_xor_sync(0xffffffffu, s, o);

    const float inv = 1.f / s;
    unsigned* ph = g_coef_hi + (size_t)wid * KP_;
    unsigned* pl = g_coef_lo + (size_t)wid * KP_;
    #pragma unroll
    for (int k = 0; k < 7; k++) {
        float mine = v[k] * inv;
        float partner = __shfl_xor_sync(0xffffffffu, mine, 1);
        int kp = (lane >> 1) + 16 * k;
        if ((lane & 1) == 0 && kp < KP_) {
            unsigned hi, lo;
            split_h2(make_float2(mine, partner), hi, lo);
            ph[kp] = hi;
            pl[kp] = lo;
        }
    }
}

// -----------------------------------------------------------------------------
// Kernel C (HMMA pool): pure cp.async fill from pre-split hi/lo arrays.
// grid (32 d-tiles of 32, 16 b), block 160.
// -----------------------------------------------------------------------------
#define PDT  32
#define KPS  108

__global__ __launch_bounds__(160) void pool_kernel(float* __restrict__ out)
{
    extern __shared__ unsigned psm[];
    unsigned* ch = psm;
    unsigned* cl = ch + C_ * KPS;
    unsigned* ih = cl + C_ * KPS;
    unsigned* il = ih + PDT * KPS;

    const int tid  = threadIdx.x;
    const int warp = tid >> 5;
    const int lane = tid & 31;
    const int q    = lane & 3;
    const int g    = lane >> 2;
    const int d0   = blockIdx.x * PDT;
    const int b    = blockIdx.y;

    unsigned sbase;
    asm("{ .reg .u64 t; cvta.to.shared.u64 t, %1; cvt.u32.u64 %0, t; }"
        : "=r"(sbase) : "l"(psm));

    for (int i = tid; i < C_ * 26; i += 160) {
        int row = i / 26, cq = i - row * 26;
        unsigned soff = (row * KPS + cq * 4) * 4;
        size_t  goff = ((size_t)b * C_ + row) * KP_ + cq * 4;
        asm volatile("cp.async.ca.shared.global [%0], [%1], 16;"
                     :: "r"(sbase + soff), "l"(g_coef_hi + goff));
        asm volatile("cp.async.ca.shared.global [%0], [%1], 16;"
                     :: "r"(sbase + (unsigned)(C_ * KPS * 4) + soff),
                        "l"(g_coef_lo + goff));
    }
    const unsigned ih_off = 2u * C_ * KPS * 4;
    for (int i = tid; i < PDT * 26; i += 160) {
        int row = i / 26, cq = i - row * 26;
        unsigned soff = (row * KPS + cq * 4) * 4;
        size_t  goff = ((size_t)b * D_ + d0 + row) * KP_ + cq * 4;
        asm volatile("cp.async.ca.shared.global [%0], [%1], 16;"
                     :: "r"(sbase + ih_off + soff), "l"(g_imgT_hi + goff));
        asm volatile("cp.async.ca.shared.global [%0], [%1], 16;"
                     :: "r"(sbase + ih_off + (unsigned)(PDT * KPS * 4) + soff),
                        "l"(g_imgT_lo + goff));
    }
    asm volatile("cp.async.commit_group;");
    asm volatile("cp.async.wait_group 0;");
    __syncthreads();

    float acc[4][4];
    #pragma unroll
    for (int t = 0; t < 4; t++)
        #pragma unroll
        for (int r = 0; r < 4; r++) acc[t][r] = 0.f;

    const int rA0 = (warp * 16 + g) * KPS;
    const int rA1 = (warp * 16 + g + 8) * KPS;

    #pragma unroll 1
    for (int ks = 0; ks < 13; ks++) {
        const int p0 = ks * 8 + q;
        const int p1 = p0 + 4;
        const unsigned ah0 = ch[rA0 + p0], ah1 = ch[rA1 + p0];
        const unsigned ah2 = ch[rA0 + p1], ah3 = ch[rA1 + p1];
        const unsigned al0 = cl[rA0 + p0], al1 = cl[rA1 + p0];
        const unsigned al2 = cl[rA0 + p1], al3 = cl[rA1 + p1];

        #pragma unroll
        for (int t = 0; t < 4; t++) {
            const int rB = (t * 8 + g) * KPS;
            const unsigned bh0 = ih[rB + p0], bh1 = ih[rB + p1];
            const unsigned bl0 = il[rB + p0], bl1 = il[rB + p1];
            MMA16816(acc[t][0], acc[t][1], acc[t][2], acc[t][3],
                     ah0, ah1, ah2, ah3, bh0, bh1);
            MMA16816(acc[t][0], acc[t][1], acc[t][2], acc[t][3],
                     ah0, ah1, ah2, ah3, bl0, bl1);
            MMA16816(acc[t][0], acc[t][1], acc[t][2], acc[t][3],
                     al0, al1, al2, al3, bh0, bh1);
        }
    }

    #pragma unroll
    for (int t = 0; t < 4; t++) {
        const int dcol = d0 + t * 8 + 2 * q;
        const size_t r0 = ((size_t)b * C_ + warp * 16 + g) * D_ + dcol;
        const size_t r1 = ((size_t)b * C_ + warp * 16 + g + 8) * D_ + dcol;
        *(float2*)&out[r0] = make_float2(acc[t][0], acc[t][1]);
        *(float2*)&out[r1] = make_float2(acc[t][2], acc[t][3]);
    }
}

// -----------------------------------------------------------------------------

extern "C" void kernel_launch(void* const* d_in, const int* in_sizes, int n_in,
                              void* d_out, int out_size)
{
    const float* img  = (const float*)d_in[1];
    const float* word = (const float*)d_in[2];
    const float* fw   = (const float*)d_in[3];
    float* out = (float*)d_out;

    const int pool_smem = (2 * C_ + 2 * PDT) * KPS * (int)sizeof(unsigned); // 96768
    cudaFuncSetAttribute(pool_kernel, cudaFuncAttributeMaxDynamicSharedMemorySize,
                         pool_smem);

    pack_all<<<P1_BLOCKS + P2_BLOCKS + P3_BLOCKS, 256>>>(img, word, fw);

    scores_kernel<<<dim3(13, 5, B_ * NSPL), 128>>>();

    softmax_kernel<<<160, 256>>>();

    pool_kernel<<<dim3(D_ / PDT, B_), 160, pool_smem>>>(out);
}

// round 10
// speedup vs baseline: 1.0996x; 1.0074x over previous
#include <cuda_runtime.h>
#include <cuda_fp16.h>
#include <cuda_bf16.h>

#define B_     16
#define C_     80
#define D_     1024
#define HW_    196
#define HWP_   208
#define NSPL   4
#define DCHUNK (D_ / NSPL)    // 256 d = 128 pairs per scores block
#define KP_    104            // hw-pairs (208/2)

__device__ float    g_part[B_ * C_ * NSPL * HW_];
__device__ unsigned g_img2[B_ * (D_ / 2) * HWP_];     // f16x2 d-pairs (scores)
__device__ unsigned g_word2[C_ * (D_ / 2)];           // f16x2 d-pairs (scores)
__device__ unsigned g_fwh2[D_ / 2];                   // f16x2 d-pairs (scores)
__device__ unsigned g_coef_hi[B_ * C_ * KP_];         // f16x2 hw-pairs (pool)
__device__ unsigned g_imgT_hi[B_ * D_ * KP_];         // f16x2 hw-pairs (pool)
__device__ unsigned g_imgT_lo[B_ * D_ * KP_];

__device__ __forceinline__ unsigned pack_h2(float a, float b) {
    unsigned r;
    asm("cvt.rn.f16x2.f32 %0, %2, %1;" : "=r"(r) : "f"(a), "f"(b));
    return r;
}
__device__ __forceinline__ unsigned tanh_h2(unsigned x) {
    unsigned y;
    asm("tanh.approx.f16x2 %0, %1;" : "=r"(y) : "r"(x));
    return y;
}
__device__ __forceinline__ unsigned mul_h2(unsigned a, unsigned b) {
    unsigned y;
    asm("mul.rn.f16x2 %0, %1, %2;" : "=r"(y) : "r"(a), "r"(b));
    return y;
}
__device__ __forceinline__ void split_h2(float2 v, unsigned& hi, unsigned& lo) {
    __half2 h = __float22half2_rn(v);
    float2 hf = __half22float2(h);
    __half2 l = __float22half2_rn(make_float2(v.x - hf.x, v.y - hf.y));
    hi = *(unsigned*)&h;
    lo = *(unsigned*)&l;
}

#define MMA16816(D0,D1,D2,D3, A0,A1,A2,A3, B0,B1) \
    asm("mma.sync.aligned.m16n8k16.row.col.f32.f16.f16.f32 " \
        "{%0,%1,%2,%3}, {%4,%5,%6,%7}, {%8,%9}, {%0,%1,%2,%3};" \
        : "+f"(D0), "+f"(D1), "+f"(D2), "+f"(D3) \
        : "r"(A0), "r"(A1), "r"(A2), "r"(A3), "r"(B0), "r"(B1))

// -----------------------------------------------------------------------------
// Kernel P (merged): phase 1 -> g_img2, phase 2 -> g_imgT hi/lo,
// phase 3 -> g_word2 + g_fwh2.
// -----------------------------------------------------------------------------
#define P1_BLOCKS 1664   // 16*512*52 / 256
#define P2_BLOCKS 832    // 16*1024*13 / 256
#define P3_BLOCKS 162    // (80*512 + 512) / 256
__global__ __launch_bounds__(256) void pack_all(
    const float* __restrict__ img,
    const float* __restrict__ word,
    const float* __restrict__ fw)
{
    const int blk = blockIdx.x;
    const int tid = threadIdx.x;

    if (blk < P1_BLOCKS) {
        int idx = blk * 256 + tid;
        int hw4 = idx % 52;
        int t   = idx / 52;
        int dp  = t & 511;
        int b   = t >> 9;
        uint4 o = make_uint4(0u, 0u, 0u, 0u);
        if (hw4 < 49) {
            const float* p = img + ((size_t)b * D_ + 2 * dp) * HW_ + hw4 * 4;
            float4 a = *(const float4*)p;
            float4 c = *(const float4*)(p + HW_);
            o.x = pack_h2(a.x, c.x);
            o.y = pack_h2(a.y, c.y);
            o.z = pack_h2(a.z, c.z);
            o.w = pack_h2(a.w, c.w);
        }
        *(uint4*)&g_img2[((size_t)b * (D_ / 2) + dp) * HWP_ + hw4 * 4] = o;
    } else if (blk < P1_BLOCKS + P2_BLOCKS) {
        int idx = (blk - P1_BLOCKS) * 256 + tid;
        int ks = idx % 13;
        int t  = idx / 13;
        int d  = t & (D_ - 1);
        int b  = t >> 10;
        const float* row = img + ((size_t)b * D_ + d) * HW_;
        float v[16];
        if (ks < 12) {
            #pragma unroll
            for (int j = 0; j < 4; j++) {
                float4 f = *(const float4*)(row + ks * 16 + j * 4);
                v[4*j] = f.x; v[4*j+1] = f.y; v[4*j+2] = f.z; v[4*j+3] = f.w;
            }
        } else {
            float4 f = *(const float4*)(row + 192);
            v[0] = f.x; v[1] = f.y; v[2] = f.z; v[3] = f.w;
            #pragma unroll
            for (int j = 4; j < 16; j++) v[j] = 0.f;
        }
        unsigned hi[8], lo[8];
        #pragma unroll
        for (int j = 0; j < 8; j++)
            split_h2(make_float2(v[2*j], v[2*j+1]), hi[j], lo[j]);
        unsigned* ph = g_imgT_hi + ((size_t)b * D_ + d) * KP_ + ks * 8;
        unsigned* pl = g_imgT_lo + ((size_t)b * D_ + d) * KP_ + ks * 8;
        *(uint4*)ph       = make_uint4(hi[0], hi[1], hi[2], hi[3]);
        *(uint4*)(ph + 4) = make_uint4(hi[4], hi[5], hi[6], hi[7]);
        *(uint4*)pl       = make_uint4(lo[0], lo[1], lo[2], lo[3]);
        *(uint4*)(pl + 4) = make_uint4(lo[4], lo[5], lo[6], lo[7]);
    } else {
        int idx = (blk - P1_BLOCKS - P2_BLOCKS) * 256 + tid;
        if (idx < C_ * (D_ / 2)) {
            int c = idx >> 9, dp = idx & 511;
            float2 w = *(const float2*)&word[(size_t)c * D_ + 2 * dp];
            g_word2[c * (D_ / 2) + dp] = pack_h2(w.x, w.y);
        } else {
            int dp = idx - C_ * (D_ / 2);   // < 512
            g_fwh2[dp] = pack_h2(fw[2 * dp], fw[2 * dp + 1]);
        }
    }
}

// -----------------------------------------------------------------------------
// Kernel A: partial scores via HMMA. Fill = pure cp.async.
// grid (13 hw16, 5 c16, B*NSPL), block 128. 16 kc steps.
// -----------------------------------------------------------------------------
__global__ __launch_bounds__(128) void scores_kernel()
{
    __shared__ unsigned img2_s[128][24];
    __shared__ unsigned word2_s[16][128];
    __shared__ unsigned fwh2_s[128];

    const int tid  = threadIdx.x;
    const int warp = tid >> 5;
    const int lane = tid & 31;
    const int q    = lane & 3;
    const int g    = lane >> 2;
    const int hw0  = blockIdx.x * 16;
    const int c0   = blockIdx.y * 16;
    const int b    = blockIdx.z & (B_ - 1);
    const int spl  = blockIdx.z >> 4;
    const int dp0  = spl * (DCHUNK / 2);

    unsigned sb_img, sb_word, sb_fw;
    asm("{ .reg .u64 t; cvta.to.shared.u64 t, %1; cvt.u32.u64 %0, t; }"
        : "=r"(sb_img) : "l"(&img2_s[0][0]));
    asm("{ .reg .u64 t; cvta.to.shared.u64 t, %1; cvt.u32.u64 %0, t; }"
        : "=r"(sb_word) : "l"(&word2_s[0][0]));
    asm("{ .reg .u64 t; cvta.to.shared.u64 t, %1; cvt.u32.u64 %0, t; }"
        : "=r"(sb_fw) : "l"(&fwh2_s[0]));

    #pragma unroll
    for (int k = 0; k < 4; k++) {
        int ch  = tid + k * 128;
        int dp  = ch >> 2;
        int off = ch & 3;
        asm volatile("cp.async.ca.shared.global [%0], [%1], 16;"
            :: "r"(sb_img + (dp * 24 + off * 4) * 4),
               "l"(g_img2 + ((size_t)b * (D_ / 2) + dp0 + dp) * HWP_ + hw0 + off * 4));
    }
    #pragma unroll
    for (int k = 0; k < 4; k++) {
        int ch = tid + k * 128;
        int row = ch >> 5;
        int cq  = ch & 31;
        asm volatile("cp.async.ca.shared.global [%0], [%1], 16;"
            :: "r"(sb_word + (row * 128 + cq * 4) * 4),
               "l"(g_word2 + (size_t)(c0 + row) * (D_ / 2) + dp0 + cq * 4));
    }
    if (tid < 32)
        asm volatile("cp.async.ca.shared.global [%0], [%1], 16;"
            :: "r"(sb_fw + tid * 16), "l"(g_fwh2 + dp0 + tid * 4));

    asm volatile("cp.async.commit_group;");
    asm volatile("cp.async.wait_group 0;");
    __syncthreads();

    float dacc[4][4];
    #pragma unroll
    for (int j = 0; j < 4; j++)
        #pragma unroll
        for (int r = 0; r < 4; r++) dacc[j][r] = 0.f;

    const bool bsel = (lane < 4);

    #pragma unroll 4
    for (int kc = 0; kc < 16; kc++) {
        const int p0 = kc * 8 + q;
        const int p1 = p0 + 4;
        const unsigned iv00 = img2_s[p0][g];
        const unsigned iv01 = img2_s[p0][g + 8];
        const unsigned iv10 = img2_s[p1][g];
        const unsigned iv11 = img2_s[p1][g + 8];
        const unsigned fb0 = bsel ? fwh2_s[p0] : 0u;
        const unsigned fb1 = bsel ? fwh2_s[p1] : 0u;

        #pragma unroll
        for (int j = 0; j < 4; j++) {
            const int cl = warp * 4 + j;
            const unsigned wA = word2_s[cl][p0];
            const unsigned wB = word2_s[cl][p1];
            unsigned a0 = tanh_h2(mul_h2(iv00, wA));
            unsigned a1 = tanh_h2(mul_h2(iv01, wA));
            unsigned a2 = tanh_h2(mul_h2(iv10, wB));
            unsigned a3 = tanh_h2(mul_h2(iv11, wB));
            MMA16816(dacc[j][0], dacc[j][1], dacc[j][2], dacc[j][3],
                     a0, a1, a2, a3, fb0, fb1);
        }
    }

    if (q == 0) {
        #pragma unroll
        for (int j = 0; j < 4; j++) {
            const int c = c0 + warp * 4 + j;
            const size_t rowbase = (((size_t)b * C_ + c) * NSPL + spl) * HW_;
            const int hw1 = hw0 + g;
            const int hw2 = hw0 + g + 8;
            if (hw1 < HW_) g_part[rowbase + hw1] = dacc[j][0];
            if (hw2 < HW_) g_part[rowbase + hw2] = dacc[j][2];
        }
    }
}

// -----------------------------------------------------------------------------
// Kernel B: sum NSPL partials, softmax, emit coef hi f16x2 pairs only.
// -----------------------------------------------------------------------------
__global__ __launch_bounds__(256) void softmax_kernel()
{
    const int wid  = (blockIdx.x * blockDim.x + threadIdx.x) >> 5;
    const int lane = threadIdx.x & 31;
    if (wid >= B_ * C_) return;

    const float* part = g_part + (size_t)wid * NSPL * HW_;

    float v[7];
    float m = -1e30f;
    #pragma unroll
    for (int k = 0; k < 7; k++) {
        int i = lane + 32 * k;
        float s = -1e30f;
        if (i < HW_) {
            s = 0.f;
            #pragma unroll
            for (int p = 0; p < NSPL; p++) s += part[p * HW_ + i];
        }
        v[k] = s;
        m = fmaxf(m, s);
    }
    #pragma unroll
    for (int o = 16; o; o >>= 1) m = fmaxf(m, __shfl_xor_sync(0xffffffffu, m, o));

    float s = 0.f;
    #pragma unroll
    for (int k = 0; k < 7; k++) { v[k] = __expf(v[k] - m); s += v[k]; }
    #pragma unroll
    for (int o = 16; o; o >>= 1) s += __shfl_xor_sync(0xffffffffu, s, o);

    const float inv = 1.f / s;
    unsigned* ph = g_coef_hi + (size_t)wid * KP_;
    #pragma unroll
    for (int k = 0; k < 7; k++) {
        float mine = v[k] * inv;
        float partner = __shfl_xor_sync(0xffffffffu, mine, 1);
        int kp = (lane >> 1) + 16 * k;
        if ((lane & 1) == 0 && kp < KP_)
            ph[kp] = pack_h2(mine, partner);
    }
}

// -----------------------------------------------------------------------------
// Kernel C (HMMA pool): coef f16 (hi only), img split hi/lo.
// Two cp.async groups: {coef,img_hi} then {img_lo}; AhBh pass overlaps the
// img_lo arrival. smem 62 KB -> 3 blocks/SM.
// grid (32 d-tiles of 32, 16 b), block 160.
// -----------------------------------------------------------------------------
#define PDT  32
#define KPS  108

__global__ __launch_bounds__(160) void pool_kernel(float* __restrict__ out)
{
    extern __shared__ unsigned psm[];
    unsigned* ch = psm;                  // coef hi [80][KPS]
    unsigned* ih = ch + C_ * KPS;        // img  hi [PDT][KPS]
    unsigned* il = ih + PDT * KPS;       // img  lo [PDT][KPS]

    const int tid  = threadIdx.x;
    const int warp = tid >> 5;
    const int lane = tid & 31;
    const int q    = lane & 3;
    const int g    = lane >> 2;
    const int d0   = blockIdx.x * PDT;
    const int b    = blockIdx.y;

    unsigned sbase;
    asm("{ .reg .u64 t; cvta.to.shared.u64 t, %1; cvt.u32.u64 %0, t; }"
        : "=r"(sbase) : "l"(psm));
    const unsigned ih_off = (unsigned)(C_ * KPS * 4);
    const unsigned il_off = ih_off + (unsigned)(PDT * KPS * 4);

    // group 1: coef hi + img hi
    for (int i = tid; i < C_ * 26; i += 160) {
        int row = i / 26, cq = i - row * 26;
        asm volatile("cp.async.ca.shared.global [%0], [%1], 16;"
            :: "r"(sbase + (row * KPS + cq * 4) * 4),
               "l"(g_coef_hi + ((size_t)b * C_ + row) * KP_ + cq * 4));
    }
    for (int i = tid; i < PDT * 26; i += 160) {
        int row = i / 26, cq = i - row * 26;
        asm volatile("cp.async.ca.shared.global [%0], [%1], 16;"
            :: "r"(sbase + ih_off + (row * KPS + cq * 4) * 4),
               "l"(g_imgT_hi + ((size_t)b * D_ + d0 + row) * KP_ + cq * 4));
    }
    asm volatile("cp.async.commit_group;");
    // group 2: img lo
    for (int i = tid; i < PDT * 26; i += 160) {
        int row = i / 26, cq = i - row * 26;
        asm volatile("cp.async.ca.shared.global [%0], [%1], 16;"
            :: "r"(sbase + il_off + (row * KPS + cq * 4) * 4),
               "l"(g_imgT_lo + ((size_t)b * D_ + d0 + row) * KP_ + cq * 4));
    }
    asm volatile("cp.async.commit_group;");

    float acc[4][4];
    #pragma unroll
    for (int t = 0; t < 4; t++)
        #pragma unroll
        for (int r = 0; r < 4; r++) acc[t][r] = 0.f;

    const int rA0 = (warp * 16 + g) * KPS;
    const int rA1 = (warp * 16 + g + 8) * KPS;

    asm volatile("cp.async.wait_group 1;");
    __syncthreads();

    // pass 1: coef_hi x img_hi
    #pragma unroll 1
    for (int ks = 0; ks < 13; ks++) {
        const int p0 = ks * 8 + q;
        const int p1 = p0 + 4;
        const unsigned ah0 = ch[rA0 + p0], ah1 = ch[rA1 + p0];
        const unsigned ah2 = ch[rA0 + p1], ah3 = ch[rA1 + p1];
        #pragma unroll
        for (int t = 0; t < 4; t++) {
            const int rB = (t * 8 + g) * KPS;
            MMA16816(acc[t][0], acc[t][1], acc[t][2], acc[t][3],
                     ah0, ah1, ah2, ah3, ih[rB + p0], ih[rB + p1]);
        }
    }

    asm volatile("cp.async.wait_group 0;");
    __syncthreads();

    // pass 2: coef_hi x img_lo
    #pragma unroll 1
    for (int ks = 0; ks < 13; ks++) {
        const int p0 = ks * 8 + q;
        const int p1 = p0 + 4;
        const unsigned ah0 = ch[rA0 + p0], ah1 = ch[rA1 + p0];
        const unsigned ah2 = ch[rA0 + p1], ah3 = ch[rA1 + p1];
        #pragma unroll
        for (int t = 0; t < 4; t++) {
            const int rB = (t * 8 + g) * KPS;
            MMA16816(acc[t][0], acc[t][1], acc[t][2], acc[t][3],
                     ah0, ah1, ah2, ah3, il[rB + p0], il[rB + p1]);
        }
    }

    #pragma unroll
    for (int t = 0; t < 4; t++) {
        const int dcol = d0 + t * 8 + 2 * q;
        const size_t r0 = ((size_t)b * C_ + warp * 16 + g) * D_ + dcol;
        const size_t r1 = ((size_t)b * C_ + warp * 16 + g + 8) * D_ + dcol;
        *(float2*)&out[r0] = make_float2(acc[t][0], acc[t][1]);
        *(float2*)&out[r1] = make_float2(acc[t][2], acc[t][3]);
    }
}

// -----------------------------------------------------------------------------

extern "C" void kernel_launch(void* const* d_in, const int* in_sizes, int n_in,
                              void* d_out, int out_size)
{
    const float* img  = (const float*)d_in[1];
    const float* word = (const float*)d_in[2];
    const float* fw   = (const float*)d_in[3];
    float* out = (float*)d_out;

    const int pool_smem = (C_ + 2 * PDT) * KPS * (int)sizeof(unsigned); // 62208
    cudaFuncSetAttribute(pool_kernel, cudaFuncAttributeMaxDynamicSharedMemorySize,
                         pool_smem);

    pack_all<<<P1_BLOCKS + P2_BLOCKS + P3_BLOCKS, 256>>>(img, word, fw);

    scores_kernel<<<dim3(13, 5, B_ * NSPL), 128>>>();

    softmax_kernel<<<160, 256>>>();

    pool_kernel<<<dim3(D_ / PDT, B_), 160, pool_smem>>>(out);
}

// round 11
// speedup vs baseline: 1.1491x; 1.0450x over previous
#include <cuda_runtime.h>
#include <cuda_fp16.h>
#include <cuda_bf16.h>

#define B_     16
#define C_     80
#define D_     1024
#define HW_    196
#define HWP_   208
#define NSPL   4
#define DCHUNK (D_ / NSPL)    // 256 d = 128 pairs per scores block
#define KP_    104            // hw-pairs (208/2)

__device__ float    g_part[B_ * C_ * NSPL * HW_];
__device__ unsigned g_img2[B_ * (D_ / 2) * HWP_];     // f16x2 d-pairs (scores)
__device__ unsigned g_word2[C_ * (D_ / 2)];           // f16x2 d-pairs (scores)
__device__ unsigned g_fwh2[D_ / 2];                   // f16x2 d-pairs (scores)
__device__ unsigned g_coef_hi[B_ * C_ * KP_];         // f16x2 hw-pairs (pool)
__device__ unsigned g_imgT_hi[B_ * D_ * KP_];         // f16x2 hw-pairs (pool)
__device__ unsigned g_imgT_lo[B_ * D_ * KP_];

__device__ __forceinline__ unsigned pack_h2(float a, float b) {
    unsigned r;
    asm("cvt.rn.f16x2.f32 %0, %2, %1;" : "=r"(r) : "f"(a), "f"(b));
    return r;
}
__device__ __forceinline__ unsigned tanh_h2(unsigned x) {
    unsigned y;
    asm("tanh.approx.f16x2 %0, %1;" : "=r"(y) : "r"(x));
    return y;
}
__device__ __forceinline__ unsigned mul_h2(unsigned a, unsigned b) {
    unsigned y;
    asm("mul.rn.f16x2 %0, %1, %2;" : "=r"(y) : "r"(a), "r"(b));
    return y;
}
__device__ __forceinline__ void split_h2(float2 v, unsigned& hi, unsigned& lo) {
    __half2 h = __float22half2_rn(v);
    float2 hf = __half22float2(h);
    __half2 l = __float22half2_rn(make_float2(v.x - hf.x, v.y - hf.y));
    hi = *(unsigned*)&h;
    lo = *(unsigned*)&l;
}

#define MMA16816(D0,D1,D2,D3, A0,A1,A2,A3, B0,B1) \
    asm("mma.sync.aligned.m16n8k16.row.col.f32.f16.f16.f32 " \
        "{%0,%1,%2,%3}, {%4,%5,%6,%7}, {%8,%9}, {%0,%1,%2,%3};" \
        : "+f"(D0), "+f"(D1), "+f"(D2), "+f"(D3) \
        : "r"(A0), "r"(A1), "r"(A2), "r"(A3), "r"(B0), "r"(B1))

// -----------------------------------------------------------------------------
// Kernel P (merged): phase 1 -> g_img2, phase 2 -> g_imgT hi/lo,
// phase 3 -> g_word2 + g_fwh2.
// -----------------------------------------------------------------------------
#define P1_BLOCKS 1664   // 16*512*52 / 256
#define P2_BLOCKS 832    // 16*1024*13 / 256
#define P3_BLOCKS 162    // (80*512 + 512) / 256
__global__ __launch_bounds__(256) void pack_all(
    const float* __restrict__ img,
    const float* __restrict__ word,
    const float* __restrict__ fw)
{
    const int blk = blockIdx.x;
    const int tid = threadIdx.x;

    if (blk < P1_BLOCKS) {
        int idx = blk * 256 + tid;
        int hw4 = idx % 52;
        int t   = idx / 52;
        int dp  = t & 511;
        int b   = t >> 9;
        uint4 o = make_uint4(0u, 0u, 0u, 0u);
        if (hw4 < 49) {
            const float* p = img + ((size_t)b * D_ + 2 * dp) * HW_ + hw4 * 4;
            float4 a = *(const float4*)p;
            float4 c = *(const float4*)(p + HW_);
            o.x = pack_h2(a.x, c.x);
            o.y = pack_h2(a.y, c.y);
            o.z = pack_h2(a.z, c.z);
            o.w = pack_h2(a.w, c.w);
        }
        *(uint4*)&g_img2[((size_t)b * (D_ / 2) + dp) * HWP_ + hw4 * 4] = o;
    } else if (blk < P1_BLOCKS + P2_BLOCKS) {
        int idx = (blk - P1_BLOCKS) * 256 + tid;
        int ks = idx % 13;
        int t  = idx / 13;
        int d  = t & (D_ - 1);
        int b  = t >> 10;
        const float* row = img + ((size_t)b * D_ + d) * HW_;
        float v[16];
        if (ks < 12) {
            #pragma unroll
            for (int j = 0; j < 4; j++) {
                float4 f = *(const float4*)(row + ks * 16 + j * 4);
                v[4*j] = f.x; v[4*j+1] = f.y; v[4*j+2] = f.z; v[4*j+3] = f.w;
            }
        } else {
            float4 f = *(const float4*)(row + 192);
            v[0] = f.x; v[1] = f.y; v[2] = f.z; v[3] = f.w;
            #pragma unroll
            for (int j = 4; j < 16; j++) v[j] = 0.f;
        }
        unsigned hi[8], lo[8];
        #pragma unroll
        for (int j = 0; j < 8; j++)
            split_h2(make_float2(v[2*j], v[2*j+1]), hi[j], lo[j]);
        unsigned* ph = g_imgT_hi + ((size_t)b * D_ + d) * KP_ + ks * 8;
        unsigned* pl = g_imgT_lo + ((size_t)b * D_ + d) * KP_ + ks * 8;
        *(uint4*)ph       = make_uint4(hi[0], hi[1], hi[2], hi[3]);
        *(uint4*)(ph + 4) = make_uint4(hi[4], hi[5], hi[6], hi[7]);
        *(uint4*)pl       = make_uint4(lo[0], lo[1], lo[2], lo[3]);
        *(uint4*)(pl + 4) = make_uint4(lo[4], lo[5], lo[6], lo[7]);
    } else {
        int idx = (blk - P1_BLOCKS - P2_BLOCKS) * 256 + tid;
        if (idx < C_ * (D_ / 2)) {
            int c = idx >> 9, dp = idx & 511;
            float2 w = *(const float2*)&word[(size_t)c * D_ + 2 * dp];
            g_word2[c * (D_ / 2) + dp] = pack_h2(w.x, w.y);
        } else {
            int dp = idx - C_ * (D_ / 2);   // < 512
            g_fwh2[dp] = pack_h2(fw[2 * dp], fw[2 * dp + 1]);
        }
    }
}

// -----------------------------------------------------------------------------
// Kernel A: partial scores via HMMA. Fill = pure cp.async.
// grid (13 hw16, 5 c16, B*NSPL), block 128. 16 kc steps.
// -----------------------------------------------------------------------------
__global__ __launch_bounds__(128) void scores_kernel()
{
    __shared__ unsigned img2_s[128][24];
    __shared__ unsigned word2_s[16][128];
    __shared__ unsigned fwh2_s[128];

    const int tid  = threadIdx.x;
    const int warp = tid >> 5;
    const int lane = tid & 31;
    const int q    = lane & 3;
    const int g    = lane >> 2;
    const int hw0  = blockIdx.x * 16;
    const int c0   = blockIdx.y * 16;
    const int b    = blockIdx.z & (B_ - 1);
    const int spl  = blockIdx.z >> 4;
    const int dp0  = spl * (DCHUNK / 2);

    unsigned sb_img, sb_word, sb_fw;
    asm("{ .reg .u64 t; cvta.to.shared.u64 t, %1; cvt.u32.u64 %0, t; }"
        : "=r"(sb_img) : "l"(&img2_s[0][0]));
    asm("{ .reg .u64 t; cvta.to.shared.u64 t, %1; cvt.u32.u64 %0, t; }"
        : "=r"(sb_word) : "l"(&word2_s[0][0]));
    asm("{ .reg .u64 t; cvta.to.shared.u64 t, %1; cvt.u32.u64 %0, t; }"
        : "=r"(sb_fw) : "l"(&fwh2_s[0]));

    #pragma unroll
    for (int k = 0; k < 4; k++) {
        int ch  = tid + k * 128;
        int dp  = ch >> 2;
        int off = ch & 3;
        asm volatile("cp.async.ca.shared.global [%0], [%1], 16;"
            :: "r"(sb_img + (dp * 24 + off * 4) * 4),
               "l"(g_img2 + ((size_t)b * (D_ / 2) + dp0 + dp) * HWP_ + hw0 + off * 4));
    }
    #pragma unroll
    for (int k = 0; k < 4; k++) {
        int ch = tid + k * 128;
        int row = ch >> 5;
        int cq  = ch & 31;
        asm volatile("cp.async.ca.shared.global [%0], [%1], 16;"
            :: "r"(sb_word + (row * 128 + cq * 4) * 4),
               "l"(g_word2 + (size_t)(c0 + row) * (D_ / 2) + dp0 + cq * 4));
    }
    if (tid < 32)
        asm volatile("cp.async.ca.shared.global [%0], [%1], 16;"
            :: "r"(sb_fw + tid * 16), "l"(g_fwh2 + dp0 + tid * 4));

    asm volatile("cp.async.commit_group;");
    asm volatile("cp.async.wait_group 0;");
    __syncthreads();

    float dacc[4][4];
    #pragma unroll
    for (int j = 0; j < 4; j++)
        #pragma unroll
        for (int r = 0; r < 4; r++) dacc[j][r] = 0.f;

    const bool bsel = (lane < 4);

    #pragma unroll 4
    for (int kc = 0; kc < 16; kc++) {
        const int p0 = kc * 8 + q;
        const int p1 = p0 + 4;
        const unsigned iv00 = img2_s[p0][g];
        const unsigned iv01 = img2_s[p0][g + 8];
        const unsigned iv10 = img2_s[p1][g];
        const unsigned iv11 = img2_s[p1][g + 8];
        const unsigned fb0 = bsel ? fwh2_s[p0] : 0u;
        const unsigned fb1 = bsel ? fwh2_s[p1] : 0u;

        #pragma unroll
        for (int j = 0; j < 4; j++) {
            const int cl = warp * 4 + j;
            const unsigned wA = word2_s[cl][p0];
            const unsigned wB = word2_s[cl][p1];
            unsigned a0 = tanh_h2(mul_h2(iv00, wA));
            unsigned a1 = tanh_h2(mul_h2(iv01, wA));
            unsigned a2 = tanh_h2(mul_h2(iv10, wB));
            unsigned a3 = tanh_h2(mul_h2(iv11, wB));
            MMA16816(dacc[j][0], dacc[j][1], dacc[j][2], dacc[j][3],
                     a0, a1, a2, a3, fb0, fb1);
        }
    }

    if (q == 0) {
        #pragma unroll
        for (int j = 0; j < 4; j++) {
            const int c = c0 + warp * 4 + j;
            const size_t rowbase = (((size_t)b * C_ + c) * NSPL + spl) * HW_;
            const int hw1 = hw0 + g;
            const int hw2 = hw0 + g + 8;
            if (hw1 < HW_) g_part[rowbase + hw1] = dacc[j][0];
            if (hw2 < HW_) g_part[rowbase + hw2] = dacc[j][2];
        }
    }
}

// -----------------------------------------------------------------------------
// Kernel B: sum NSPL partials, softmax, emit coef hi f16x2 pairs only.
// -----------------------------------------------------------------------------
__global__ __launch_bounds__(256) void softmax_kernel()
{
    const int wid  = (blockIdx.x * blockDim.x + threadIdx.x) >> 5;
    const int lane = threadIdx.x & 31;
    if (wid >= B_ * C_) return;

    const float* part = g_part + (size_t)wid * NSPL * HW_;

    float v[7];
    float m = -1e30f;
    #pragma unroll
    for (int k = 0; k < 7; k++) {
        int i = lane + 32 * k;
        float s = -1e30f;
        if (i < HW_) {
            s = 0.f;
            #pragma unroll
            for (int p = 0; p < NSPL; p++) s += part[p * HW_ + i];
        }
        v[k] = s;
        m = fmaxf(m, s);
    }
    #pragma unroll
    for (int o = 16; o; o >>= 1) m = fmaxf(m, __shfl_xor_sync(0xffffffffu, m, o));

    float s = 0.f;
    #pragma unroll
    for (int k = 0; k < 7; k++) { v[k] = __expf(v[k] - m); s += v[k]; }
    #pragma unroll
    for (int o = 16; o; o >>= 1) s += __shfl_xor_sync(0xffffffffu, s, o);

    const float inv = 1.f / s;
    unsigned* ph = g_coef_hi + (size_t)wid * KP_;
    #pragma unroll
    for (int k = 0; k < 7; k++) {
        float mine = v[k] * inv;
        float partner = __shfl_xor_sync(0xffffffffu, mine, 1);
        int kp = (lane >> 1) + 16 * k;
        if ((lane & 1) == 0 && kp < KP_)
            ph[kp] = pack_h2(mine, partner);
    }
}

// -----------------------------------------------------------------------------
// Kernel C (HMMA pool): coef f16 (hi), img split hi/lo. PDT=64, 320 threads
// (10 warps = 2 d-halves x 5 class-tiles). 2 blocks/SM, grid = 1 wave.
// Two cp.async groups: {coef,img_hi} then {img_lo}.
// grid (16 d-tiles of 64, 16 b), block 320.
// -----------------------------------------------------------------------------
#define PDT  64
#define KPS  108

__global__ __launch_bounds__(320) void pool_kernel(float* __restrict__ out)
{
    extern __shared__ unsigned psm[];
    unsigned* ch = psm;                  // coef hi [80][KPS]
    unsigned* ih = ch + C_ * KPS;        // img  hi [PDT][KPS]
    unsigned* il = ih + PDT * KPS;       // img  lo [PDT][KPS]

    const int tid  = threadIdx.x;
    const int warp = tid >> 5;
    const int lane = tid & 31;
    const int q    = lane & 3;
    const int g    = lane >> 2;
    const int wg   = warp / 5;           // d-half: 0 or 1
    const int wi   = warp % 5;           // class tile
    const int d0   = blockIdx.x * PDT;
    const int b    = blockIdx.y;

    unsigned sbase;
    asm("{ .reg .u64 t; cvta.to.shared.u64 t, %1; cvt.u32.u64 %0, t; }"
        : "=r"(sbase) : "l"(psm));
    const unsigned ih_off = (unsigned)(C_ * KPS * 4);
    const unsigned il_off = ih_off + (unsigned)(PDT * KPS * 4);

    // group 1: coef hi + img hi
    for (int i = tid; i < C_ * 26; i += 320) {
        int row = i / 26, cq = i - row * 26;
        asm volatile("cp.async.ca.shared.global [%0], [%1], 16;"
            :: "r"(sbase + (row * KPS + cq * 4) * 4),
               "l"(g_coef_hi + ((size_t)b * C_ + row) * KP_ + cq * 4));
    }
    for (int i = tid; i < PDT * 26; i += 320) {
        int row = i / 26, cq = i - row * 26;
        asm volatile("cp.async.ca.shared.global [%0], [%1], 16;"
            :: "r"(sbase + ih_off + (row * KPS + cq * 4) * 4),
               "l"(g_imgT_hi + ((size_t)b * D_ + d0 + row) * KP_ + cq * 4));
    }
    asm volatile("cp.async.commit_group;");
    // group 2: img lo
    for (int i = tid; i < PDT * 26; i += 320) {
        int row = i / 26, cq = i - row * 26;
        asm volatile("cp.async.ca.shared.global [%0], [%1], 16;"
            :: "r"(sbase + il_off + (row * KPS + cq * 4) * 4),
               "l"(g_imgT_lo + ((size_t)b * D_ + d0 + row) * KP_ + cq * 4));
    }
    asm volatile("cp.async.commit_group;");

    float acc[4][4];
    #pragma unroll
    for (int t = 0; t < 4; t++)
        #pragma unroll
        for (int r = 0; r < 4; r++) acc[t][r] = 0.f;

    const int rA0 = (wi * 16 + g) * KPS;
    const int rA1 = (wi * 16 + g + 8) * KPS;
    const int dbase = wg * 32;

    asm volatile("cp.async.wait_group 1;");
    __syncthreads();

    // pass 1: coef_hi x img_hi
    #pragma unroll 1
    for (int ks = 0; ks < 13; ks++) {
        const int p0 = ks * 8 + q;
        const int p1 = p0 + 4;
        const unsigned ah0 = ch[rA0 + p0], ah1 = ch[rA1 + p0];
        const unsigned ah2 = ch[rA0 + p1], ah3 = ch[rA1 + p1];
        #pragma unroll
        for (int t = 0; t < 4; t++) {
            const int rB = (dbase + t * 8 + g) * KPS;
            MMA16816(acc[t][0], acc[t][1], acc[t][2], acc[t][3],
                     ah0, ah1, ah2, ah3, ih[rB + p0], ih[rB + p1]);
        }
    }

    asm volatile("cp.async.wait_group 0;");
    __syncthreads();

    // pass 2: coef_hi x img_lo
    #pragma unroll 1
    for (int ks = 0; ks < 13; ks++) {
        const int p0 = ks * 8 + q;
        const int p1 = p0 + 4;
        const unsigned ah0 = ch[rA0 + p0], ah1 = ch[rA1 + p0];
        const unsigned ah2 = ch[rA0 + p1], ah3 = ch[rA1 + p1];
        #pragma unroll
        for (int t = 0; t < 4; t++) {
            const int rB = (dbase + t * 8 + g) * KPS;
            MMA16816(acc[t][0], acc[t][1], acc[t][2], acc[t][3],
                     ah0, ah1, ah2, ah3, il[rB + p0], il[rB + p1]);
        }
    }

    #pragma unroll
    for (int t = 0; t < 4; t++) {
        const int dcol = d0 + dbase + t * 8 + 2 * q;
        const size_t r0 = ((size_t)b * C_ + wi * 16 + g) * D_ + dcol;
        const size_t r1 = ((size_t)b * C_ + wi * 16 + g + 8) * D_ + dcol;
        *(float2*)&out[r0] = make_float2(acc[t][0], acc[t][1]);
        *(float2*)&out[r1] = make_float2(acc[t][2], acc[t][3]);
    }
}

// -----------------------------------------------------------------------------

extern "C" void kernel_launch(void* const* d_in, const int* in_sizes, int n_in,
                              void* d_out, int out_size)
{
    const float* img  = (const float*)d_in[1];
    const float* word = (const float*)d_in[2];
    const float* fw   = (const float*)d_in[3];
    float* out = (float*)d_out;

    const int pool_smem = (C_ + 2 * PDT) * KPS * (int)sizeof(unsigned); // 89856
    cudaFuncSetAttribute(pool_kernel, cudaFuncAttributeMaxDynamicSharedMemorySize,
                         pool_smem);

    pack_all<<<P1_BLOCKS + P2_BLOCKS + P3_BLOCKS, 256>>>(img, word, fw);

    scores_kernel<<<dim3(13, 5, B_ * NSPL), 128>>>();

    softmax_kernel<<<160, 256>>>();

    pool_kernel<<<dim3(D_ / PDT, B_), 320, pool_smem>>>(out);
}

// round 12
// speedup vs baseline: 1.2092x; 1.0523x over previous
#include <cuda_runtime.h>
#include <cuda_fp16.h>
#include <cuda_bf16.h>

#define B_     16
#define C_     80
#define D_     1024
#define HW_    196
#define HWP_   208
#define NSPL   2
#define KP_    104            // hw-pairs (208/2)

__device__ float    g_part[B_ * C_ * NSPL * HW_];
__device__ unsigned g_img2[B_ * (D_ / 2) * HWP_];     // f16x2 d-pairs (scores)
__device__ unsigned g_word2[C_ * (D_ / 2)];           // f16x2 d-pairs (scores)
__device__ unsigned g_fwh2[D_ / 2];                   // f16x2 d-pairs (scores)
__device__ unsigned g_coef_hi[B_ * C_ * KP_];         // f16x2 hw-pairs (pool)
__device__ unsigned g_imgT_hi[B_ * D_ * KP_];         // f16x2 hw-pairs (pool)

__device__ __forceinline__ unsigned pack_h2(float a, float b) {
    unsigned r;
    asm("cvt.rn.f16x2.f32 %0, %2, %1;" : "=r"(r) : "f"(a), "f"(b));
    return r;
}
__device__ __forceinline__ unsigned tanh_h2(unsigned x) {
    unsigned y;
    asm("tanh.approx.f16x2 %0, %1;" : "=r"(y) : "r"(x));
    return y;
}
__device__ __forceinline__ unsigned mul_h2(unsigned a, unsigned b) {
    unsigned y;
    asm("mul.rn.f16x2 %0, %1, %2;" : "=r"(y) : "r"(a), "r"(b));
    return y;
}

#define MMA16816(D0,D1,D2,D3, A0,A1,A2,A3, B0,B1) \
    asm("mma.sync.aligned.m16n8k16.row.col.f32.f16.f16.f32 " \
        "{%0,%1,%2,%3}, {%4,%5,%6,%7}, {%8,%9}, {%0,%1,%2,%3};" \
        : "+f"(D0), "+f"(D1), "+f"(D2), "+f"(D3) \
        : "r"(A0), "r"(A1), "r"(A2), "r"(A3), "r"(B0), "r"(B1))

#define CPA16(saddr, gptr) \
    asm volatile("cp.async.ca.shared.global [%0], [%1], 16;" \
                 :: "r"(saddr), "l"(gptr))

// -----------------------------------------------------------------------------
// Kernel P: merged packing. Phase A: img read ONCE -> g_img2 (d-pairs) AND
// g_imgT_hi (hw-pairs). thread = (b, dpair, ks<13) covering 16 hw of 2 d rows.
// Phase B: word/fw -> f16x2.
// -----------------------------------------------------------------------------
#define PA_BLOCKS 416    // 16*512*13 / 256
#define PB_BLOCKS 162    // (80*512 + 512) / 256
__global__ __launch_bounds__(256) void pack_all(
    const float* __restrict__ img,
    const float* __restrict__ word,
    const float* __restrict__ fw)
{
    const int blk = blockIdx.x;
    const int tid = threadIdx.x;

    if (blk < PA_BLOCKS) {
        int idx = blk * 256 + tid;       // < 16*512*13
        int ks = idx % 13;
        int t  = idx / 13;
        int dp = t & 511;
        int b  = t >> 9;

        const float* r0 = img + ((size_t)b * D_ + 2 * dp) * HW_ + ks * 16;
        const float* r1 = r0 + HW_;
        float a[16], c[16];
        if (ks < 12) {
            #pragma unroll
            for (int j = 0; j < 4; j++) {
                float4 fa = *(const float4*)(r0 + 4 * j);
                float4 fc = *(const float4*)(r1 + 4 * j);
                a[4*j] = fa.x; a[4*j+1] = fa.y; a[4*j+2] = fa.z; a[4*j+3] = fa.w;
                c[4*j] = fc.x; c[4*j+1] = fc.y; c[4*j+2] = fc.z; c[4*j+3] = fc.w;
            }
        } else {
            float4 fa = *(const float4*)r0;
            float4 fc = *(const float4*)r1;
            a[0] = fa.x; a[1] = fa.y; a[2] = fa.z; a[3] = fa.w;
            c[0] = fc.x; c[1] = fc.y; c[2] = fc.z; c[3] = fc.w;
            #pragma unroll
            for (int j = 4; j < 16; j++) { a[j] = 0.f; c[j] = 0.f; }
        }

        // g_img2: d-paired, [b][dp][hw]
        unsigned* pi = &g_img2[((size_t)b * (D_ / 2) + dp) * HWP_ + ks * 16];
        #pragma unroll
        for (int j = 0; j < 4; j++) {
            uint4 o;
            o.x = pack_h2(a[4*j],   c[4*j]);
            o.y = pack_h2(a[4*j+1], c[4*j+1]);
            o.z = pack_h2(a[4*j+2], c[4*j+2]);
            o.w = pack_h2(a[4*j+3], c[4*j+3]);
            *(uint4*)(pi + 4 * j) = o;
        }
        // g_imgT_hi: hw-paired rows 2dp and 2dp+1
        unsigned* p0 = g_imgT_hi + ((size_t)b * D_ + 2 * dp) * KP_ + ks * 8;
        unsigned* p1 = p0 + KP_;
        uint4 oa0, oa1, oc0, oc1;
        oa0.x = pack_h2(a[0], a[1]);  oa0.y = pack_h2(a[2], a[3]);
        oa0.z = pack_h2(a[4], a[5]);  oa0.w = pack_h2(a[6], a[7]);
        oa1.x = pack_h2(a[8], a[9]);  oa1.y = pack_h2(a[10], a[11]);
        oa1.z = pack_h2(a[12], a[13]); oa1.w = pack_h2(a[14], a[15]);
        oc0.x = pack_h2(c[0], c[1]);  oc0.y = pack_h2(c[2], c[3]);
        oc0.z = pack_h2(c[4], c[5]);  oc0.w = pack_h2(c[6], c[7]);
        oc1.x = pack_h2(c[8], c[9]);  oc1.y = pack_h2(c[10], c[11]);
        oc1.z = pack_h2(c[12], c[13]); oc1.w = pack_h2(c[14], c[15]);
        *(uint4*)p0       = oa0;
        *(uint4*)(p0 + 4) = oa1;
        *(uint4*)p1       = oc0;
        *(uint4*)(p1 + 4) = oc1;
    } else {
        int idx = (blk - PA_BLOCKS) * 256 + tid;
        if (idx < C_ * (D_ / 2)) {
            int c = idx >> 9, dp = idx & 511;
            float2 w = *(const float2*)&word[(size_t)c * D_ + 2 * dp];
            g_word2[c * (D_ / 2) + dp] = pack_h2(w.x, w.y);
        } else {
            int dp = idx - C_ * (D_ / 2);   // < 512
            g_fwh2[dp] = pack_h2(fw[2 * dp], fw[2 * dp + 1]);
        }
    }
}

// -----------------------------------------------------------------------------
// Kernel A: partial scores via HMMA, double-buffered cp.async pipeline.
// NSPL=2: each block reduces 256 dpairs as 4 sub-chunks of 64, prefetching
// sub-chunk c+1 while computing c.
// grid (13 hw16, 5 c16, B*NSPL), block 128 (4 warps x 4 classes).
// -----------------------------------------------------------------------------
__global__ __launch_bounds__(128) void scores_kernel()
{
    __shared__ unsigned img2_s[2][64][24];   // [buf][dpair][hw(16)+pad8]
    __shared__ unsigned word2_s[2][16][64];  // [buf][cc][dpair]
    __shared__ unsigned fwh2_s[2][64];       // [buf][dpair]

    const int tid  = threadIdx.x;
    const int warp = tid >> 5;
    const int lane = tid & 31;
    const int q    = lane & 3;
    const int g    = lane >> 2;
    const int hw0  = blockIdx.x * 16;
    const int c0   = blockIdx.y * 16;
    const int b    = blockIdx.z & (B_ - 1);
    const int spl  = blockIdx.z >> 4;
    const int dpbase = spl * 256;            // 256 dpairs per block

    unsigned sb_img, sb_word, sb_fw;
    asm("{ .reg .u64 t; cvta.to.shared.u64 t, %1; cvt.u32.u64 %0, t; }"
        : "=r"(sb_img) : "l"(&img2_s[0][0][0]));
    asm("{ .reg .u64 t; cvta.to.shared.u64 t, %1; cvt.u32.u64 %0, t; }"
        : "=r"(sb_word) : "l"(&word2_s[0][0][0]));
    asm("{ .reg .u64 t; cvta.to.shared.u64 t, %1; cvt.u32.u64 %0, t; }"
        : "=r"(sb_fw) : "l"(&fwh2_s[0][0]));

    const unsigned IMG_BUF  = 64 * 24 * 4;
    const unsigned WORD_BUF = 16 * 64 * 4;
    const unsigned FW_BUF   = 64 * 4;

    // fill sub-chunk c into buffer c&1 (all 128 threads), then commit
    #define FILL(c) do {                                                        \
        const int buf_ = (c) & 1;                                               \
        const int dp0_ = dpbase + (c) * 64;                                     \
        _Pragma("unroll")                                                       \
        for (int k = 0; k < 2; k++) {                                           \
            int ch  = tid + k * 128;                                            \
            int dp  = ch >> 2;                                                  \
            int off = ch & 3;                                                   \
            CPA16(sb_img + buf_ * IMG_BUF + (dp * 24 + off * 4) * 4,            \
                  g_img2 + ((size_t)b * (D_ / 2) + dp0_ + dp) * HWP_ + hw0 + off * 4); \
        }                                                                       \
        _Pragma("unroll")                                                       \
        for (int k = 0; k < 2; k++) {                                           \
            int ch  = tid + k * 128;                                            \
            int row = ch >> 4;                                                  \
            int cq  = ch & 15;                                                  \
            CPA16(sb_word + buf_ * WORD_BUF + (row * 64 + cq * 4) * 4,          \
                  g_word2 + (size_t)(c0 + row) * (D_ / 2) + dp0_ + cq * 4);     \
        }                                                                       \
        if (tid < 16)                                                           \
            CPA16(sb_fw + buf_ * FW_BUF + tid * 16, g_fwh2 + dp0_ + tid * 4);   \
        asm volatile("cp.async.commit_group;");                                 \
    } while (0)

    float dacc[4][4];
    #pragma unroll
    for (int j = 0; j < 4; j++)
        #pragma unroll
        for (int r = 0; r < 4; r++) dacc[j][r] = 0.f;

    const bool bsel = (lane < 4);

    FILL(0);

    #pragma unroll
    for (int c = 0; c < 4; c++) {
        if (c < 3) {
            FILL(c + 1);
            asm volatile("cp.async.wait_group 1;");
        } else {
            asm volatile("cp.async.wait_group 0;");
        }
        __syncthreads();

        const int buf = c & 1;
        #pragma unroll 4
        for (int kc = 0; kc < 8; kc++) {
            const int p0 = kc * 8 + q;
            const int p1 = p0 + 4;
            const unsigned iv00 = img2_s[buf][p0][g];
            const unsigned iv01 = img2_s[buf][p0][g + 8];
            const unsigned iv10 = img2_s[buf][p1][g];
            const unsigned iv11 = img2_s[buf][p1][g + 8];
            const unsigned fb0 = bsel ? fwh2_s[buf][p0] : 0u;
            const unsigned fb1 = bsel ? fwh2_s[buf][p1] : 0u;

            #pragma unroll
            for (int j = 0; j < 4; j++) {
                const int cl = warp * 4 + j;
                const unsigned wA = word2_s[buf][cl][p0];
                const unsigned wB = word2_s[buf][cl][p1];
                unsigned a0 = tanh_h2(mul_h2(iv00, wA));
                unsigned a1 = tanh_h2(mul_h2(iv01, wA));
                unsigned a2 = tanh_h2(mul_h2(iv10, wB));
                unsigned a3 = tanh_h2(mul_h2(iv11, wB));
                MMA16816(dacc[j][0], dacc[j][1], dacc[j][2], dacc[j][3],
                         a0, a1, a2, a3, fb0, fb1);
            }
        }
        __syncthreads();
    }

    if (q == 0) {
        #pragma unroll
        for (int j = 0; j < 4; j++) {
            const int c = c0 + warp * 4 + j;
            const size_t rowbase = (((size_t)b * C_ + c) * NSPL + spl) * HW_;
            const int hw1 = hw0 + g;
            const int hw2 = hw0 + g + 8;
            if (hw1 < HW_) g_part[rowbase + hw1] = dacc[j][0];
            if (hw2 < HW_) g_part[rowbase + hw2] = dacc[j][2];
        }
    }
    #undef FILL
}

// -----------------------------------------------------------------------------
// Kernel B: sum NSPL partials, softmax, emit coef hi f16x2 pairs.
// -----------------------------------------------------------------------------
__global__ __launch_bounds__(256) void softmax_kernel()
{
    const int wid  = (blockIdx.x * blockDim.x + threadIdx.x) >> 5;
    const int lane = threadIdx.x & 31;
    if (wid >= B_ * C_) return;

    const float* part = g_part + (size_t)wid * NSPL * HW_;

    float v[7];
    float m = -1e30f;
    #pragma unroll
    for (int k = 0; k < 7; k++) {
        int i = lane + 32 * k;
        float s = -1e30f;
        if (i < HW_) {
            s = 0.f;
            #pragma unroll
            for (int p = 0; p < NSPL; p++) s += part[p * HW_ + i];
        }
        v[k] = s;
        m = fmaxf(m, s);
    }
    #pragma unroll
    for (int o = 16; o; o >>= 1) m = fmaxf(m, __shfl_xor_sync(0xffffffffu, m, o));

    float s = 0.f;
    #pragma unroll
    for (int k = 0; k < 7; k++) { v[k] = __expf(v[k] - m); s += v[k]; }
    #pragma unroll
    for (int o = 16; o; o >>= 1) s += __shfl_xor_sync(0xffffffffu, s, o);

    const float inv = 1.f / s;
    unsigned* ph = g_coef_hi + (size_t)wid * KP_;
    #pragma unroll
    for (int k = 0; k < 7; k++) {
        float mine = v[k] * inv;
        float partner = __shfl_xor_sync(0xffffffffu, mine, 1);
        int kp = (lane >> 1) + 16 * k;
        if ((lane & 1) == 0 && kp < KP_)
            ph[kp] = pack_h2(mine, partner);
    }
}

// -----------------------------------------------------------------------------
// Kernel C (HMMA pool): coef f16 x img f16 (hi only). Single pass.
// smem 62 KB -> 3 blocks/SM. grid (16 d-tiles of 64, 16 b), block 320.
// -----------------------------------------------------------------------------
#define PDT  64
#define KPS  108

__global__ __launch_bounds__(320) void pool_kernel(float* __restrict__ out)
{
    extern __shared__ unsigned psm[];
    unsigned* ch = psm;                  // coef hi [80][KPS]
    unsigned* ih = ch + C_ * KPS;        // img  hi [PDT][KPS]

    const int tid  = threadIdx.x;
    const int warp = tid >> 5;
    const int lane = tid & 31;
    const int q    = lane & 3;
    const int g    = lane >> 2;
    const int wg   = warp / 5;           // d-half: 0 or 1
    const int wi   = warp % 5;           // class tile
    const int d0   = blockIdx.x * PDT;
    const int b    = blockIdx.y;

    unsigned sbase;
    asm("{ .reg .u64 t; cvta.to.shared.u64 t, %1; cvt.u32.u64 %0, t; }"
        : "=r"(sbase) : "l"(psm));
    const unsigned ih_off = (unsigned)(C_ * KPS * 4);

    for (int i = tid; i < C_ * 26; i += 320) {
        int row = i / 26, cq = i - row * 26;
        CPA16(sbase + (row * KPS + cq * 4) * 4,
              g_coef_hi + ((size_t)b * C_ + row) * KP_ + cq * 4);
    }
    for (int i = tid; i < PDT * 26; i += 320) {
        int row = i / 26, cq = i - row * 26;
        CPA16(sbase + ih_off + (row * KPS + cq * 4) * 4,
              g_imgT_hi + ((size_t)b * D_ + d0 + row) * KP_ + cq * 4);
    }
    asm volatile("cp.async.commit_group;");

    float acc[4][4];
    #pragma unroll
    for (int t = 0; t < 4; t++)
        #pragma unroll
        for (int r = 0; r < 4; r++) acc[t][r] = 0.f;

    const int rA0 = (wi * 16 + g) * KPS;
    const int rA1 = (wi * 16 + g + 8) * KPS;
    const int dbase = wg * 32;

    asm volatile("cp.async.wait_group 0;");
    __syncthreads();

    #pragma unroll 1
    for (int ks = 0; ks < 13; ks++) {
        const int p0 = ks * 8 + q;
        const int p1 = p0 + 4;
        const unsigned ah0 = ch[rA0 + p0], ah1 = ch[rA1 + p0];
        const unsigned ah2 = ch[rA0 + p1], ah3 = ch[rA1 + p1];
        #pragma unroll
        for (int t = 0; t < 4; t++) {
            const int rB = (dbase + t * 8 + g) * KPS;
            MMA16816(acc[t][0], acc[t][1], acc[t][2], acc[t][3],
                     ah0, ah1, ah2, ah3, ih[rB + p0], ih[rB + p1]);
        }
    }

    #pragma unroll
    for (int t = 0; t < 4; t++) {
        const int dcol = d0 + dbase + t * 8 + 2 * q;
        const size_t r0 = ((size_t)b * C_ + wi * 16 + g) * D_ + dcol;
        const size_t r1 = ((size_t)b * C_ + wi * 16 + g + 8) * D_ + dcol;
        *(float2*)&out[r0] = make_float2(acc[t][0], acc[t][1]);
        *(float2*)&out[r1] = make_float2(acc[t][2], acc[t][3]);
    }
}

// -----------------------------------------------------------------------------

extern "C" void kernel_launch(void* const* d_in, const int* in_sizes, int n_in,
                              void* d_out, int out_size)
{
    const float* img  = (const float*)d_in[1];
    const float* word = (const float*)d_in[2];
    const float* fw   = (const float*)d_in[3];
    float* out = (float*)d_out;

    const int pool_smem = (C_ + PDT) * KPS * (int)sizeof(unsigned); // 62208
    cudaFuncSetAttribute(pool_kernel, cudaFuncAttributeMaxDynamicSharedMemorySize,
                         pool_smem);

    pack_all<<<PA_BLOCKS + PB_BLOCKS, 256>>>(img, word, fw);

    scores_kernel<<<dim3(13, 5, B_ * NSPL), 128>>>();

    softmax_kernel<<<160, 256>>>();

    pool_kernel<<<dim3(D_ / PDT, B_), 320, pool_smem>>>(out);
}